// round 1
// baseline (speedup 1.0000x reference)
#include <cuda_runtime.h>

#define B_   8
#define S_   1024
#define E_   1152
#define H_   16
#define D_   72
#define NROW (B_ * S_)          // 8192
#define W3E  (3 * E_)           // 3456

// Scratch (allocation-free rule: __device__ globals)
__device__ float g_Q[B_ * H_ * S_ * D_];   // [b,h,s,d]
__device__ float g_K[B_ * H_ * S_ * D_];
__device__ float g_V[B_ * H_ * S_ * D_];
__device__ float g_A[NROW * E_];           // attention out, row-major [b*s, h*d]

// ---------------------------------------------------------------------------
// Kernel 1: QKV projection.  grid (8192/64, 1152/64, 3), 256 threads.
// C[row,col] = X[row,:] @ W[:, z*1152+col] + bias, scattered to [b,h,s,d].
// ---------------------------------------------------------------------------
__global__ void __launch_bounds__(256, 2) qkv_gemm(
    const float* __restrict__ q, const float* __restrict__ k,
    const float* __restrict__ v, const float* __restrict__ W,
    const float* __restrict__ bias)
{
    const int z = blockIdx.z;
    const float* X = (z == 0) ? q : (z == 1) ? k : v;
    float* Out = (z == 0) ? g_Q : (z == 1) ? g_K : g_V;

    const int rowBase = blockIdx.x * 64;
    const int colBase = blockIdx.y * 64;
    const int wcol0   = z * E_ + colBase;

    __shared__ __align__(16) float As[16][64];
    __shared__ __align__(16) float Bs[16][64];

    const int tid = threadIdx.x;
    const int tx = tid & 15, ty = tid >> 4;
    const int ar = tid >> 2, ak = (tid & 3) * 4;   // A tile: 64 rows x 16 k
    const int bk = tid >> 4, bc = (tid & 15) * 4;  // B tile: 16 k x 64 cols

    float acc[4][4];
#pragma unroll
    for (int i = 0; i < 4; i++)
#pragma unroll
        for (int j = 0; j < 4; j++) acc[i][j] = 0.0f;

    for (int kt = 0; kt < E_; kt += 16) {
        float4 av = *(const float4*)&X[(rowBase + ar) * E_ + kt + ak];
        float4 bv = *(const float4*)&W[(kt + bk) * W3E + wcol0 + bc];
        As[ak + 0][ar] = av.x; As[ak + 1][ar] = av.y;
        As[ak + 2][ar] = av.z; As[ak + 3][ar] = av.w;
        *(float4*)&Bs[bk][bc] = bv;
        __syncthreads();
#pragma unroll
        for (int kk = 0; kk < 16; kk++) {
            float4 a4 = *(const float4*)&As[kk][ty * 4];
            float4 b4 = *(const float4*)&Bs[kk][tx * 4];
            float a[4] = {a4.x, a4.y, a4.z, a4.w};
            float b[4] = {b4.x, b4.y, b4.z, b4.w};
#pragma unroll
            for (int i = 0; i < 4; i++)
#pragma unroll
                for (int j = 0; j < 4; j++) acc[i][j] += a[i] * b[j];
        }
        __syncthreads();
    }

#pragma unroll
    for (int i = 0; i < 4; i++) {
        const int row = rowBase + ty * 4 + i;
        const int b   = row >> 10;
        const int s   = row & 1023;
#pragma unroll
        for (int j = 0; j < 4; j++) {
            const int col = colBase + tx * 4 + j;
            const int h   = col / D_;
            const int d   = col - h * D_;
            Out[((b * H_ + h) * S_ + s) * D_ + d] = acc[i][j] + bias[z * E_ + col];
        }
    }
}

// ---------------------------------------------------------------------------
// Kernel 2: flash attention. grid (S/64, H, B), 64 threads.
// Each thread owns one query row; K/V staged in SMEM in tiles of 32 keys.
// ---------------------------------------------------------------------------
__global__ void __launch_bounds__(64) attn_kernel()
{
    const int qt = blockIdx.x;   // 64-query tile
    const int h  = blockIdx.y;
    const int b  = blockIdx.z;
    const int t  = threadIdx.x;  // query row within tile

    const float scale = 0.11785113019775792f;  // 72^-0.5

    __shared__ __align__(16) float Ks[32 * D_];
    __shared__ __align__(16) float Vs[32 * D_];
    __shared__ float Ss[64 * 33];              // padded rows, conflict-free

    const float* qrow = g_Q + ((size_t)((b * H_ + h) * S_) + qt * 64 + t) * D_;
    float qr[D_];
#pragma unroll
    for (int d = 0; d < D_; d += 4) {
        float4 qv = *(const float4*)&qrow[d];
        qr[d + 0] = qv.x * scale; qr[d + 1] = qv.y * scale;
        qr[d + 2] = qv.z * scale; qr[d + 3] = qv.w * scale;
    }

    float O[D_];
#pragma unroll
    for (int d = 0; d < D_; d++) O[d] = 0.0f;
    float m = -3.0e38f, l = 0.0f;

    const float* Kbh = g_K + (size_t)((b * H_ + h) * S_) * D_;
    const float* Vbh = g_V + (size_t)((b * H_ + h) * S_) * D_;

    for (int ktile = 0; ktile < S_; ktile += 32) {
        __syncthreads();
        // cooperative load 32x72 K and V tiles (576 float4 each)
        const float4* Kg = (const float4*)(Kbh + (size_t)ktile * D_);
        const float4* Vg = (const float4*)(Vbh + (size_t)ktile * D_);
#pragma unroll
        for (int i = 0; i < 9; i++) {
            ((float4*)Ks)[t + i * 64] = Kg[t + i * 64];
            ((float4*)Vs)[t + i * 64] = Vg[t + i * 64];
        }
        __syncthreads();

        // scores for this thread's row vs 32 keys
        float mt = -3.0e38f;
        for (int j = 0; j < 32; j++) {
            float acc = 0.0f;
            const float* kr = &Ks[j * D_];
#pragma unroll
            for (int d = 0; d < D_; d += 4) {
                float4 kk = *(const float4*)&kr[d];
                acc += qr[d] * kk.x + qr[d + 1] * kk.y
                     + qr[d + 2] * kk.z + qr[d + 3] * kk.w;
            }
            Ss[t * 33 + j] = acc;
            mt = fmaxf(mt, acc);
        }

        const float m_new = fmaxf(m, mt);
        const float alpha = __expf(m - m_new);
        float lsum = 0.0f;
        for (int j = 0; j < 32; j++) {
            float p = __expf(Ss[t * 33 + j] - m_new);
            Ss[t * 33 + j] = p;
            lsum += p;
        }
        l = l * alpha + lsum;
#pragma unroll
        for (int d = 0; d < D_; d++) O[d] *= alpha;

        for (int j = 0; j < 32; j++) {
            const float p = Ss[t * 33 + j];
            const float* vr = &Vs[j * D_];
#pragma unroll
            for (int d = 0; d < D_; d += 4) {
                float4 vv = *(const float4*)&vr[d];
                O[d + 0] += p * vv.x; O[d + 1] += p * vv.y;
                O[d + 2] += p * vv.z; O[d + 3] += p * vv.w;
            }
        }
        m = m_new;
    }

    // store to g_A row-major [b*S+s, h*D+d]
    const float inv_l = 1.0f / l;
    float* arow = g_A + (size_t)((b * S_) + qt * 64 + t) * E_ + h * D_;
#pragma unroll
    for (int d = 0; d < D_; d += 4) {
        float4 ov;
        ov.x = O[d + 0] * inv_l; ov.y = O[d + 1] * inv_l;
        ov.z = O[d + 2] * inv_l; ov.w = O[d + 3] * inv_l;
        *(float4*)&arow[d] = ov;
    }
}

// ---------------------------------------------------------------------------
// Kernel 3: output projection.  grid (8192/64, 1152/64), 256 threads.
// out = g_A @ out_w + out_b
// ---------------------------------------------------------------------------
__global__ void __launch_bounds__(256, 2) out_gemm(
    const float* __restrict__ W, const float* __restrict__ bias,
    float* __restrict__ out)
{
    const int rowBase = blockIdx.x * 64;
    const int colBase = blockIdx.y * 64;

    __shared__ __align__(16) float As[16][64];
    __shared__ __align__(16) float Bs[16][64];

    const int tid = threadIdx.x;
    const int tx = tid & 15, ty = tid >> 4;
    const int ar = tid >> 2, ak = (tid & 3) * 4;
    const int bk = tid >> 4, bc = (tid & 15) * 4;

    float acc[4][4];
#pragma unroll
    for (int i = 0; i < 4; i++)
#pragma unroll
        for (int j = 0; j < 4; j++) acc[i][j] = 0.0f;

    for (int kt = 0; kt < E_; kt += 16) {
        float4 av = *(const float4*)&g_A[(size_t)(rowBase + ar) * E_ + kt + ak];
        float4 bv = *(const float4*)&W[(kt + bk) * E_ + colBase + bc];
        As[ak + 0][ar] = av.x; As[ak + 1][ar] = av.y;
        As[ak + 2][ar] = av.z; As[ak + 3][ar] = av.w;
        *(float4*)&Bs[bk][bc] = bv;
        __syncthreads();
#pragma unroll
        for (int kk = 0; kk < 16; kk++) {
            float4 a4 = *(const float4*)&As[kk][ty * 4];
            float4 b4 = *(const float4*)&Bs[kk][tx * 4];
            float a[4] = {a4.x, a4.y, a4.z, a4.w};
            float b[4] = {b4.x, b4.y, b4.z, b4.w};
#pragma unroll
            for (int i = 0; i < 4; i++)
#pragma unroll
                for (int j = 0; j < 4; j++) acc[i][j] += a[i] * b[j];
        }
        __syncthreads();
    }

#pragma unroll
    for (int i = 0; i < 4; i++) {
        const int row = rowBase + ty * 4 + i;
        const int col = colBase + tx * 4;
        float4 ov;
        ov.x = acc[i][0] + bias[col + 0];
        ov.y = acc[i][1] + bias[col + 1];
        ov.z = acc[i][2] + bias[col + 2];
        ov.w = acc[i][3] + bias[col + 3];
        *(float4*)&out[(size_t)row * E_ + col] = ov;
    }
}

// ---------------------------------------------------------------------------
extern "C" void kernel_launch(void* const* d_in, const int* in_sizes, int n_in,
                              void* d_out, int out_size)
{
    const float* q    = (const float*)d_in[0];
    const float* k    = (const float*)d_in[1];
    const float* v    = (const float*)d_in[2];
    const float* W    = (const float*)d_in[3];
    const float* bias = (const float*)d_in[4];
    const float* ow   = (const float*)d_in[5];
    const float* ob   = (const float*)d_in[6];
    float* out = (float*)d_out;

    dim3 g1(NROW / 64, E_ / 64, 3);
    qkv_gemm<<<g1, 256>>>(q, k, v, W, bias);

    dim3 g2(S_ / 64, H_, B_);
    attn_kernel<<<g2, 64>>>();

    dim3 g3(NROW / 64, E_ / 64);
    out_gemm<<<g3, 256>>>(ow, ob, out);
}

// round 2
// speedup vs baseline: 3.6504x; 3.6504x over previous
#include <cuda_runtime.h>
#include <cstdint>

#define B_   8
#define S_   1024
#define E_   1152
#define H_   16
#define D_   72
#define NROW (B_ * S_)
#define W3E  (3 * E_)

// Scratch (allocation-free rule: __device__ globals)
__device__ float g_Q[B_ * H_ * S_ * D_];   // [b,h,s,d]
__device__ float g_K[B_ * H_ * S_ * D_];
__device__ float g_V[B_ * H_ * S_ * D_];
__device__ float g_A[NROW * E_];           // attention out, [b*s, h*d]

__device__ __forceinline__ uint32_t f2tf(float f) {
    uint32_t u;
    asm("cvt.rna.tf32.f32 %0, %1;" : "=r"(u) : "f"(f));
    return u;
}

__device__ __forceinline__ void mma_tf32(float (&c)[4],
    uint32_t a0, uint32_t a1, uint32_t a2, uint32_t a3,
    uint32_t b0, uint32_t b1)
{
    asm volatile(
        "mma.sync.aligned.m16n8k8.row.col.f32.tf32.tf32.f32 "
        "{%0,%1,%2,%3}, {%4,%5,%6,%7}, {%8,%9}, {%0,%1,%2,%3};\n"
        : "+f"(c[0]), "+f"(c[1]), "+f"(c[2]), "+f"(c[3])
        : "r"(a0), "r"(a1), "r"(a2), "r"(a3), "r"(b0), "r"(b1));
}

// ---------------------------------------------------------------------------
// QKV projection: tf32 mma, 128x128 block tile, double-buffered SMEM.
// grid (8192/128, 1152/128, 3), 256 threads (8 warps as 2m x 4n).
// ---------------------------------------------------------------------------
__global__ void __launch_bounds__(256) qkv_gemm(
    const float* __restrict__ q, const float* __restrict__ k,
    const float* __restrict__ v, const float* __restrict__ W,
    const float* __restrict__ bias)
{
    const int z = blockIdx.z;
    const float* X = (z == 0) ? q : (z == 1) ? k : v;
    float* Out = (z == 0) ? g_Q : (z == 1) ? g_K : g_V;

    const int rowBase = blockIdx.x * 128;
    const int colBase = blockIdx.y * 128;
    const int wcol0   = z * E_ + colBase;

    __shared__ __align__(16) uint32_t sA[2][16 * 136];
    __shared__ __align__(16) uint32_t sB[2][16 * 136];

    const int tid  = threadIdx.x;
    const int lane = tid & 31, warp = tid >> 5;
    const int wm = warp >> 2, wn = warp & 3;
    const int g = lane >> 2, tg = lane & 3;

    const int rowA = tid >> 2;          // 0..63 (and +64)
    const int kcA  = (tid & 3) * 4;     // k col within tile
    const int krB  = tid >> 5;          // 0..7 (and +8)
    const int ncB  = (tid & 31) * 4;    // n col within tile

    float acc[4][4][4];
#pragma unroll
    for (int i = 0; i < 4; i++)
#pragma unroll
        for (int j = 0; j < 4; j++)
#pragma unroll
            for (int l = 0; l < 4; l++) acc[i][j][l] = 0.0f;

    float4 a0v, a1v, b0v, b1v;
    auto gload = [&](int kt) {
        a0v = *(const float4*)&X[(size_t)(rowBase + rowA) * E_ + kt + kcA];
        a1v = *(const float4*)&X[(size_t)(rowBase + rowA + 64) * E_ + kt + kcA];
        b0v = *(const float4*)&W[(size_t)(kt + krB) * W3E + wcol0 + ncB];
        b1v = *(const float4*)&W[(size_t)(kt + krB + 8) * W3E + wcol0 + ncB];
    };
    auto sstore = [&](int st) {
        uint32_t* A  = sA[st];
        uint32_t* Bs = sB[st];
        A[(kcA + 0) * 136 + rowA] = f2tf(a0v.x);
        A[(kcA + 1) * 136 + rowA] = f2tf(a0v.y);
        A[(kcA + 2) * 136 + rowA] = f2tf(a0v.z);
        A[(kcA + 3) * 136 + rowA] = f2tf(a0v.w);
        A[(kcA + 0) * 136 + rowA + 64] = f2tf(a1v.x);
        A[(kcA + 1) * 136 + rowA + 64] = f2tf(a1v.y);
        A[(kcA + 2) * 136 + rowA + 64] = f2tf(a1v.z);
        A[(kcA + 3) * 136 + rowA + 64] = f2tf(a1v.w);
        *(uint4*)&Bs[krB * 136 + ncB] =
            make_uint4(f2tf(b0v.x), f2tf(b0v.y), f2tf(b0v.z), f2tf(b0v.w));
        *(uint4*)&Bs[(krB + 8) * 136 + ncB] =
            make_uint4(f2tf(b1v.x), f2tf(b1v.y), f2tf(b1v.z), f2tf(b1v.w));
    };

    gload(0);
    sstore(0);
    __syncthreads();

    int stage = 0;
    for (int kt = 0; kt < E_; kt += 16) {
        if (kt + 16 < E_) gload(kt + 16);
        const uint32_t* A  = sA[stage];
        const uint32_t* Bv = sB[stage];
#pragma unroll
        for (int ks = 0; ks < 2; ks++) {
            uint32_t af[4][4], bf[4][2];
            const int kk = ks * 8 + tg;
#pragma unroll
            for (int ma = 0; ma < 4; ma++) {
                const int m0 = wm * 64 + ma * 16 + g;
                af[ma][0] = A[kk * 136 + m0];
                af[ma][1] = A[kk * 136 + m0 + 8];
                af[ma][2] = A[(kk + 4) * 136 + m0];
                af[ma][3] = A[(kk + 4) * 136 + m0 + 8];
            }
#pragma unroll
            for (int na = 0; na < 4; na++) {
                const int n0 = wn * 32 + na * 8 + g;
                bf[na][0] = Bv[kk * 136 + n0];
                bf[na][1] = Bv[(kk + 4) * 136 + n0];
            }
#pragma unroll
            for (int ma = 0; ma < 4; ma++)
#pragma unroll
                for (int na = 0; na < 4; na++)
                    mma_tf32(acc[ma][na], af[ma][0], af[ma][1], af[ma][2],
                             af[ma][3], bf[na][0], bf[na][1]);
        }
        if (kt + 16 < E_) sstore(stage ^ 1);
        __syncthreads();
        stage ^= 1;
    }

#pragma unroll
    for (int ma = 0; ma < 4; ma++) {
#pragma unroll
        for (int na = 0; na < 4; na++) {
            const int c  = colBase + wn * 32 + na * 8 + 2 * tg;
            const float bx = bias[z * E_ + c];
            const float by = bias[z * E_ + c + 1];
            const int hh = c / D_;
            const int dd = c - hh * D_;
#pragma unroll
            for (int half = 0; half < 2; half++) {
                const int r = rowBase + wm * 64 + ma * 16 + g + half * 8;
                const int bb = r >> 10, ss = r & 1023;
                float2 ov;
                ov.x = acc[ma][na][half * 2 + 0] + bx;
                ov.y = acc[ma][na][half * 2 + 1] + by;
                *(float2*)&Out[((size_t)(bb * H_ + hh) * S_ + ss) * D_ + dd] = ov;
            }
        }
    }
}

// ---------------------------------------------------------------------------
// Flash attention, tf32 mma. grid (S/64, H, B), 128 threads (4 warps).
// Warp w owns query rows w*16..w*16+15; key tile = 32.
// ---------------------------------------------------------------------------
__global__ void __launch_bounds__(128) attn_kernel()
{
    const int qt = blockIdx.x, h = blockIdx.y, b = blockIdx.z;
    const int tid = threadIdx.x;
    const int lane = tid & 31, warp = tid >> 5;
    const int g = lane >> 2, tg = lane & 3;

    __shared__ __align__(16) uint32_t sQ[64 * 76];
    __shared__ __align__(16) uint32_t sK[32 * 76];
    __shared__ __align__(16) uint32_t sVt[72 * 40];   // V transposed [d][key]

    const float scale = 0.11785113019775792f;  // 72^-0.5
    const float* Qg = g_Q + ((size_t)(b * H_ + h) * S_ + qt * 64) * D_;
    const float* Kg = g_K + (size_t)(b * H_ + h) * S_ * D_;
    const float* Vg = g_V + (size_t)(b * H_ + h) * S_ * D_;

    // Load Q tile (scaled, tf32): 64x72 = 2304 float2, 18 per thread
#pragma unroll
    for (int i = 0; i < 18; i++) {
        const int id = tid + i * 128;
        const int r = id / 36, d = (id % 36) * 2;
        float2 qv = *(const float2*)&Qg[r * D_ + d];
        sQ[r * 76 + d]     = f2tf(qv.x * scale);
        sQ[r * 76 + d + 1] = f2tf(qv.y * scale);
    }

    float O[9][4];
#pragma unroll
    for (int i = 0; i < 9; i++)
#pragma unroll
        for (int j = 0; j < 4; j++) O[i][j] = 0.0f;
    float m0 = -3.0e38f, m1 = -3.0e38f, l0 = 0.0f, l1 = 0.0f;

    const int srcLo = (lane & ~3) | (tg >> 1);
    const int srcHi = srcLo | 2;
    const bool odd = lane & 1;

    for (int kt = 0; kt < S_; kt += 32) {
        __syncthreads();
        // load K and V tiles: 32x72 = 1152 float2, 9 per thread
#pragma unroll
        for (int i = 0; i < 9; i++) {
            const int id = tid + i * 128;
            const int r = id / 36, d = (id % 36) * 2;
            float2 kv = *(const float2*)&Kg[(size_t)(kt + r) * D_ + d];
            sK[r * 76 + d]     = f2tf(kv.x);
            sK[r * 76 + d + 1] = f2tf(kv.y);
            float2 vv = *(const float2*)&Vg[(size_t)(kt + r) * D_ + d];
            sVt[d * 40 + r]       = f2tf(vv.x);
            sVt[(d + 1) * 40 + r] = f2tf(vv.y);
        }
        __syncthreads();

        // S = Q K^T   (m=16 per warp, n=32, k=72)
        float Sc[4][4];
#pragma unroll
        for (int i = 0; i < 4; i++)
#pragma unroll
            for (int j = 0; j < 4; j++) Sc[i][j] = 0.0f;

        const int m0r = warp * 16 + g;
#pragma unroll
        for (int ks = 0; ks < 9; ks++) {
            const int kk = ks * 8 + tg;
            const uint32_t a0 = sQ[m0r * 76 + kk];
            const uint32_t a1 = sQ[(m0r + 8) * 76 + kk];
            const uint32_t a2 = sQ[m0r * 76 + kk + 4];
            const uint32_t a3 = sQ[(m0r + 8) * 76 + kk + 4];
#pragma unroll
            for (int na = 0; na < 4; na++) {
                const uint32_t b0 = sK[(na * 8 + g) * 76 + kk];
                const uint32_t b1 = sK[(na * 8 + g) * 76 + kk + 4];
                mma_tf32(Sc[na], a0, a1, a2, a3, b0, b1);
            }
        }

        // online softmax (rows r0 = m0r, r1 = m0r+8)
        float mx0 = -3.0e38f, mx1 = -3.0e38f;
#pragma unroll
        for (int na = 0; na < 4; na++) {
            mx0 = fmaxf(mx0, fmaxf(Sc[na][0], Sc[na][1]));
            mx1 = fmaxf(mx1, fmaxf(Sc[na][2], Sc[na][3]));
        }
        mx0 = fmaxf(mx0, __shfl_xor_sync(0xffffffffu, mx0, 1));
        mx0 = fmaxf(mx0, __shfl_xor_sync(0xffffffffu, mx0, 2));
        mx1 = fmaxf(mx1, __shfl_xor_sync(0xffffffffu, mx1, 1));
        mx1 = fmaxf(mx1, __shfl_xor_sync(0xffffffffu, mx1, 2));

        const float nm0 = fmaxf(m0, mx0), nm1 = fmaxf(m1, mx1);
        const float al0 = __expf(m0 - nm0), al1 = __expf(m1 - nm1);
        float s0 = 0.0f, s1 = 0.0f;
#pragma unroll
        for (int na = 0; na < 4; na++) {
            Sc[na][0] = __expf(Sc[na][0] - nm0);
            Sc[na][1] = __expf(Sc[na][1] - nm0);
            Sc[na][2] = __expf(Sc[na][2] - nm1);
            Sc[na][3] = __expf(Sc[na][3] - nm1);
            s0 += Sc[na][0] + Sc[na][1];
            s1 += Sc[na][2] + Sc[na][3];
        }
        s0 += __shfl_xor_sync(0xffffffffu, s0, 1);
        s0 += __shfl_xor_sync(0xffffffffu, s0, 2);
        s1 += __shfl_xor_sync(0xffffffffu, s1, 1);
        s1 += __shfl_xor_sync(0xffffffffu, s1, 2);
        l0 = l0 * al0 + s0;
        l1 = l1 * al1 + s1;
        m0 = nm0;
        m1 = nm1;
#pragma unroll
        for (int na = 0; na < 9; na++) {
            O[na][0] *= al0; O[na][1] *= al0;
            O[na][2] *= al1; O[na][3] *= al1;
        }

        // O += P V   (A-fragments of P built via shuffles from Sc acc layout)
#pragma unroll
        for (int ks = 0; ks < 4; ks++) {
            const float y00 = __shfl_sync(0xffffffffu, Sc[ks][0], srcLo);
            const float y01 = __shfl_sync(0xffffffffu, Sc[ks][1], srcLo);
            const float y02 = __shfl_sync(0xffffffffu, Sc[ks][0], srcHi);
            const float y03 = __shfl_sync(0xffffffffu, Sc[ks][1], srcHi);
            const float y10 = __shfl_sync(0xffffffffu, Sc[ks][2], srcLo);
            const float y11 = __shfl_sync(0xffffffffu, Sc[ks][3], srcLo);
            const float y12 = __shfl_sync(0xffffffffu, Sc[ks][2], srcHi);
            const float y13 = __shfl_sync(0xffffffffu, Sc[ks][3], srcHi);
            const uint32_t a0 = f2tf(odd ? y01 : y00);
            const uint32_t a2 = f2tf(odd ? y03 : y02);
            const uint32_t a1 = f2tf(odd ? y11 : y10);
            const uint32_t a3 = f2tf(odd ? y13 : y12);
            const int kk = ks * 8 + tg;
#pragma unroll
            for (int na = 0; na < 9; na++) {
                const uint32_t b0 = sVt[(na * 8 + g) * 40 + kk];
                const uint32_t b1 = sVt[(na * 8 + g) * 40 + kk + 4];
                mma_tf32(O[na], a0, a1, a2, a3, b0, b1);
            }
        }
    }

    // epilogue
    const float i0 = 1.0f / l0, i1 = 1.0f / l1;
    const int r0 = qt * 64 + warp * 16 + g;
    float* out0 = g_A + (size_t)(b * S_ + r0) * E_ + h * D_;
    float* out1 = g_A + (size_t)(b * S_ + r0 + 8) * E_ + h * D_;
#pragma unroll
    for (int na = 0; na < 9; na++) {
        const int c = na * 8 + 2 * tg;
        float2 o0; o0.x = O[na][0] * i0; o0.y = O[na][1] * i0;
        float2 o1; o1.x = O[na][2] * i1; o1.y = O[na][3] * i1;
        *(float2*)&out0[c] = o0;
        *(float2*)&out1[c] = o1;
    }
}

// ---------------------------------------------------------------------------
// Output projection: out = g_A @ out_w + out_b (tf32 mma, same structure).
// grid (8192/128, 1152/128), 256 threads.
// ---------------------------------------------------------------------------
__global__ void __launch_bounds__(256) out_gemm(
    const float* __restrict__ W, const float* __restrict__ bias,
    float* __restrict__ out)
{
    const int rowBase = blockIdx.x * 128;
    const int colBase = blockIdx.y * 128;

    __shared__ __align__(16) uint32_t sA[2][16 * 136];
    __shared__ __align__(16) uint32_t sB[2][16 * 136];

    const int tid  = threadIdx.x;
    const int lane = tid & 31, warp = tid >> 5;
    const int wm = warp >> 2, wn = warp & 3;
    const int g = lane >> 2, tg = lane & 3;

    const int rowA = tid >> 2;
    const int kcA  = (tid & 3) * 4;
    const int krB  = tid >> 5;
    const int ncB  = (tid & 31) * 4;

    float acc[4][4][4];
#pragma unroll
    for (int i = 0; i < 4; i++)
#pragma unroll
        for (int j = 0; j < 4; j++)
#pragma unroll
            for (int l = 0; l < 4; l++) acc[i][j][l] = 0.0f;

    float4 a0v, a1v, b0v, b1v;
    auto gload = [&](int kt) {
        a0v = *(const float4*)&g_A[(size_t)(rowBase + rowA) * E_ + kt + kcA];
        a1v = *(const float4*)&g_A[(size_t)(rowBase + rowA + 64) * E_ + kt + kcA];
        b0v = *(const float4*)&W[(size_t)(kt + krB) * E_ + colBase + ncB];
        b1v = *(const float4*)&W[(size_t)(kt + krB + 8) * E_ + colBase + ncB];
    };
    auto sstore = [&](int st) {
        uint32_t* A  = sA[st];
        uint32_t* Bs = sB[st];
        A[(kcA + 0) * 136 + rowA] = f2tf(a0v.x);
        A[(kcA + 1) * 136 + rowA] = f2tf(a0v.y);
        A[(kcA + 2) * 136 + rowA] = f2tf(a0v.z);
        A[(kcA + 3) * 136 + rowA] = f2tf(a0v.w);
        A[(kcA + 0) * 136 + rowA + 64] = f2tf(a1v.x);
        A[(kcA + 1) * 136 + rowA + 64] = f2tf(a1v.y);
        A[(kcA + 2) * 136 + rowA + 64] = f2tf(a1v.z);
        A[(kcA + 3) * 136 + rowA + 64] = f2tf(a1v.w);
        *(uint4*)&Bs[krB * 136 + ncB] =
            make_uint4(f2tf(b0v.x), f2tf(b0v.y), f2tf(b0v.z), f2tf(b0v.w));
        *(uint4*)&Bs[(krB + 8) * 136 + ncB] =
            make_uint4(f2tf(b1v.x), f2tf(b1v.y), f2tf(b1v.z), f2tf(b1v.w));
    };

    gload(0);
    sstore(0);
    __syncthreads();

    int stage = 0;
    for (int kt = 0; kt < E_; kt += 16) {
        if (kt + 16 < E_) gload(kt + 16);
        const uint32_t* A  = sA[stage];
        const uint32_t* Bv = sB[stage];
#pragma unroll
        for (int ks = 0; ks < 2; ks++) {
            uint32_t af[4][4], bf[4][2];
            const int kk = ks * 8 + tg;
#pragma unroll
            for (int ma = 0; ma < 4; ma++) {
                const int m0 = wm * 64 + ma * 16 + g;
                af[ma][0] = A[kk * 136 + m0];
                af[ma][1] = A[kk * 136 + m0 + 8];
                af[ma][2] = A[(kk + 4) * 136 + m0];
                af[ma][3] = A[(kk + 4) * 136 + m0 + 8];
            }
#pragma unroll
            for (int na = 0; na < 4; na++) {
                const int n0 = wn * 32 + na * 8 + g;
                bf[na][0] = Bv[kk * 136 + n0];
                bf[na][1] = Bv[(kk + 4) * 136 + n0];
            }
#pragma unroll
            for (int ma = 0; ma < 4; ma++)
#pragma unroll
                for (int na = 0; na < 4; na++)
                    mma_tf32(acc[ma][na], af[ma][0], af[ma][1], af[ma][2],
                             af[ma][3], bf[na][0], bf[na][1]);
        }
        if (kt + 16 < E_) sstore(stage ^ 1);
        __syncthreads();
        stage ^= 1;
    }

#pragma unroll
    for (int ma = 0; ma < 4; ma++) {
#pragma unroll
        for (int na = 0; na < 4; na++) {
            const int c = colBase + wn * 32 + na * 8 + 2 * tg;
            const float bx = bias[c];
            const float by = bias[c + 1];
#pragma unroll
            for (int half = 0; half < 2; half++) {
                const int r = rowBase + wm * 64 + ma * 16 + g + half * 8;
                float2 ov;
                ov.x = acc[ma][na][half * 2 + 0] + bx;
                ov.y = acc[ma][na][half * 2 + 1] + by;
                *(float2*)&out[(size_t)r * E_ + c] = ov;
            }
        }
    }
}

// ---------------------------------------------------------------------------
extern "C" void kernel_launch(void* const* d_in, const int* in_sizes, int n_in,
                              void* d_out, int out_size)
{
    const float* q    = (const float*)d_in[0];
    const float* k    = (const float*)d_in[1];
    const float* v    = (const float*)d_in[2];
    const float* W    = (const float*)d_in[3];
    const float* bias = (const float*)d_in[4];
    const float* ow   = (const float*)d_in[5];
    const float* ob   = (const float*)d_in[6];
    float* out = (float*)d_out;

    dim3 g1(NROW / 128, E_ / 128, 3);
    qkv_gemm<<<g1, 256>>>(q, k, v, W, bias);

    dim3 g2(S_ / 64, H_, B_);
    attn_kernel<<<g2, 128>>>();

    dim3 g3(NROW / 128, E_ / 128);
    out_gemm<<<g3, 256>>>(ow, ob, out);
}

// round 8
// speedup vs baseline: 4.1537x; 1.1379x over previous
#include <cuda_runtime.h>
#include <cstdint>

#define B_   8
#define S_   1024
#define E_   1152
#define H_   16
#define D_   72
#define NROW (B_ * S_)
#define W3E  (3 * E_)
#define CH_  (B_ * H_ * S_ * D_)

// ------- device scratch: exactly 144 MiB (R2-proven budget) -------
__device__ uint32_t g_Qs  [CH_];               // [b,h,s,d] tf32 scaled  36 MiB
__device__ uint32_t g_Ktf [CH_];               // [b,h,s,d] tf32         36 MiB
__device__ uint32_t g_Vt  [CH_];               // [b,h,d,s] tf32         36 MiB
__device__ uint32_t g_Atf [(size_t)NROW * E_]; // attn out tf32          36 MiB

// ---------------- helpers ----------------
__device__ __forceinline__ uint32_t f2tf(float f) {
    uint32_t u;
    asm("cvt.rna.tf32.f32 %0, %1;" : "=r"(u) : "f"(f));
    return u;
}
__device__ __forceinline__ void mma_tf32(float (&c)[4],
    uint32_t a0, uint32_t a1, uint32_t a2, uint32_t a3,
    uint32_t b0, uint32_t b1)
{
    asm volatile(
        "mma.sync.aligned.m16n8k8.row.col.f32.tf32.tf32.f32 "
        "{%0,%1,%2,%3}, {%4,%5,%6,%7}, {%8,%9}, {%0,%1,%2,%3};\n"
        : "+f"(c[0]), "+f"(c[1]), "+f"(c[2]), "+f"(c[3])
        : "r"(a0), "r"(a1), "r"(a2), "r"(a3), "r"(b0), "r"(b1));
}

// ---------------------------------------------------------------------------
// QKV GEMM: R2-proven mainloop (fp32 A and B, cvt at STS, double-buffered).
// New epilogue: emits attention-ready operands Qs (scaled tf32), Ktf,
// Vt (transposed [b,h,d,s]).
// grid (1152/128, 8192/128, 3), 256 threads (8 warps as 2m x 4n).
// ---------------------------------------------------------------------------
__global__ void __launch_bounds__(256) qkv_gemm(
    const float* __restrict__ q, const float* __restrict__ k,
    const float* __restrict__ v, const float* __restrict__ W,
    const float* __restrict__ bias)
{
    const int z = blockIdx.z;
    const float* X = (z == 0) ? q : (z == 1) ? k : v;

    const int rowBase = blockIdx.y * 128;
    const int colBase = blockIdx.x * 128;
    const int wcol0   = z * E_ + colBase;

    __shared__ __align__(16) uint32_t sA[2][16 * 136];
    __shared__ __align__(16) uint32_t sB[2][16 * 136];

    const int tid  = threadIdx.x;
    const int lane = tid & 31, warp = tid >> 5;
    const int wm = warp >> 2, wn = warp & 3;
    const int g = lane >> 2, tg = lane & 3;

    const int rowA = tid >> 2;          // 0..63 (and +64)
    const int kcA  = (tid & 3) * 4;
    const int krB  = tid >> 5;          // 0..7 (and +8)
    const int ncB  = (tid & 31) * 4;

    float acc[4][4][4];
#pragma unroll
    for (int i = 0; i < 4; i++)
#pragma unroll
        for (int j = 0; j < 4; j++)
#pragma unroll
            for (int l = 0; l < 4; l++) acc[i][j][l] = 0.0f;

    float4 a0v, a1v, b0v, b1v;
    a0v = *(const float4*)&X[(size_t)(rowBase + rowA) * E_ + kcA];
    a1v = *(const float4*)&X[(size_t)(rowBase + rowA + 64) * E_ + kcA];
    b0v = *(const float4*)&W[(size_t)krB * W3E + wcol0 + ncB];
    b1v = *(const float4*)&W[(size_t)(krB + 8) * W3E + wcol0 + ncB];
    {
        uint32_t* A  = sA[0];
        uint32_t* Bs = sB[0];
        A[(kcA + 0) * 136 + rowA] = f2tf(a0v.x);
        A[(kcA + 1) * 136 + rowA] = f2tf(a0v.y);
        A[(kcA + 2) * 136 + rowA] = f2tf(a0v.z);
        A[(kcA + 3) * 136 + rowA] = f2tf(a0v.w);
        A[(kcA + 0) * 136 + rowA + 64] = f2tf(a1v.x);
        A[(kcA + 1) * 136 + rowA + 64] = f2tf(a1v.y);
        A[(kcA + 2) * 136 + rowA + 64] = f2tf(a1v.z);
        A[(kcA + 3) * 136 + rowA + 64] = f2tf(a1v.w);
        *(uint4*)&Bs[krB * 136 + ncB] =
            make_uint4(f2tf(b0v.x), f2tf(b0v.y), f2tf(b0v.z), f2tf(b0v.w));
        *(uint4*)&Bs[(krB + 8) * 136 + ncB] =
            make_uint4(f2tf(b1v.x), f2tf(b1v.y), f2tf(b1v.z), f2tf(b1v.w));
    }
    __syncthreads();

    int stage = 0;
    for (int kt = 0; kt < E_; kt += 16) {
        if (kt + 16 < E_) {
            a0v = *(const float4*)&X[(size_t)(rowBase + rowA) * E_ + kt + 16 + kcA];
            a1v = *(const float4*)&X[(size_t)(rowBase + rowA + 64) * E_ + kt + 16 + kcA];
            b0v = *(const float4*)&W[(size_t)(kt + 16 + krB) * W3E + wcol0 + ncB];
            b1v = *(const float4*)&W[(size_t)(kt + 16 + krB + 8) * W3E + wcol0 + ncB];
        }
        const uint32_t* A  = sA[stage];
        const uint32_t* Bv = sB[stage];
#pragma unroll
        for (int ks = 0; ks < 2; ks++) {
            uint32_t af[4][4], bf[4][2];
            const int kk = ks * 8 + tg;
#pragma unroll
            for (int ma = 0; ma < 4; ma++) {
                const int m0 = wm * 64 + ma * 16 + g;
                af[ma][0] = A[kk * 136 + m0];
                af[ma][1] = A[kk * 136 + m0 + 8];
                af[ma][2] = A[(kk + 4) * 136 + m0];
                af[ma][3] = A[(kk + 4) * 136 + m0 + 8];
            }
#pragma unroll
            for (int na = 0; na < 4; na++) {
                const int n0 = wn * 32 + na * 8 + g;
                bf[na][0] = Bv[kk * 136 + n0];
                bf[na][1] = Bv[(kk + 4) * 136 + n0];
            }
#pragma unroll
            for (int ma = 0; ma < 4; ma++)
#pragma unroll
                for (int na = 0; na < 4; na++)
                    mma_tf32(acc[ma][na], af[ma][0], af[ma][1], af[ma][2],
                             af[ma][3], bf[na][0], bf[na][1]);
        }
        if (kt + 16 < E_) {
            uint32_t* A2  = sA[stage ^ 1];
            uint32_t* Bs2 = sB[stage ^ 1];
            A2[(kcA + 0) * 136 + rowA] = f2tf(a0v.x);
            A2[(kcA + 1) * 136 + rowA] = f2tf(a0v.y);
            A2[(kcA + 2) * 136 + rowA] = f2tf(a0v.z);
            A2[(kcA + 3) * 136 + rowA] = f2tf(a0v.w);
            A2[(kcA + 0) * 136 + rowA + 64] = f2tf(a1v.x);
            A2[(kcA + 1) * 136 + rowA + 64] = f2tf(a1v.y);
            A2[(kcA + 2) * 136 + rowA + 64] = f2tf(a1v.z);
            A2[(kcA + 3) * 136 + rowA + 64] = f2tf(a1v.w);
            *(uint4*)&Bs2[krB * 136 + ncB] =
                make_uint4(f2tf(b0v.x), f2tf(b0v.y), f2tf(b0v.z), f2tf(b0v.w));
            *(uint4*)&Bs2[(krB + 8) * 136 + ncB] =
                make_uint4(f2tf(b1v.x), f2tf(b1v.y), f2tf(b1v.z), f2tf(b1v.w));
        }
        __syncthreads();
        stage ^= 1;
    }

    // ---- epilogue: emit attention-ready tf32 operands ----
    const float scale = 0.11785113019775792f;  // 72^-0.5
#pragma unroll
    for (int ma = 0; ma < 4; ma++) {
#pragma unroll
        for (int na = 0; na < 4; na++) {
            const int c  = colBase + wn * 32 + na * 8 + 2 * tg;
            const float bx = bias[z * E_ + c];
            const float by = bias[z * E_ + c + 1];
            const int hh = c / D_;
            const int dd = c - hh * D_;
#pragma unroll
            for (int half = 0; half < 2; half++) {
                const int r = rowBase + wm * 64 + ma * 16 + g + half * 8;
                const int bb = r >> 10, ss = r & 1023;
                const float vx = acc[ma][na][half * 2 + 0] + bx;
                const float vy = acc[ma][na][half * 2 + 1] + by;
                if (z == 0) {
                    *(uint2*)&g_Qs[((size_t)(bb * H_ + hh) * S_ + ss) * D_ + dd] =
                        make_uint2(f2tf(vx * scale), f2tf(vy * scale));
                } else if (z == 1) {
                    *(uint2*)&g_Ktf[((size_t)(bb * H_ + hh) * S_ + ss) * D_ + dd] =
                        make_uint2(f2tf(vx), f2tf(vy));
                } else {
                    g_Vt[((size_t)(bb * H_ + hh) * D_ + dd) * S_ + ss]     = f2tf(vx);
                    g_Vt[((size_t)(bb * H_ + hh) * D_ + dd + 1) * S_ + ss] = f2tf(vy);
                }
            }
        }
    }
}

// ---------------------------------------------------------------------------
// Flash attention: R2 structure; cvt-free, transpose-free loaders.
// grid (S/64, H, B), 128 threads.
// ---------------------------------------------------------------------------
__global__ void __launch_bounds__(128) attn_kernel()
{
    const int qt = blockIdx.x, h = blockIdx.y, b = blockIdx.z;
    const int tid = threadIdx.x;
    const int lane = tid & 31, warp = tid >> 5;
    const int g = lane >> 2, tg = lane & 3;

    __shared__ __align__(16) uint32_t sQ[64 * 76];
    __shared__ __align__(16) uint32_t sK[32 * 76];
    __shared__ __align__(16) uint32_t sVt[72 * 40];   // [d][key]

    const uint32_t* Qg = g_Qs  + ((size_t)(b * H_ + h) * S_ + qt * 64) * D_;
    const uint32_t* Kg = g_Ktf + (size_t)(b * H_ + h) * S_ * D_;
    const uint32_t* Vg = g_Vt  + (size_t)(b * H_ + h) * D_ * S_;

#pragma unroll
    for (int i = 0; i < 18; i++) {
        const int id = tid + i * 128;
        const int r = id / 36, d = (id % 36) * 2;
        *(uint2*)&sQ[r * 76 + d] = *(const uint2*)&Qg[r * D_ + d];
    }

    float O[9][4];
#pragma unroll
    for (int i = 0; i < 9; i++)
#pragma unroll
        for (int j = 0; j < 4; j++) O[i][j] = 0.0f;
    float m0 = -3.0e38f, m1 = -3.0e38f, l0 = 0.0f, l1 = 0.0f;

    const int srcLo = (lane & ~3) | (tg >> 1);
    const int srcHi = srcLo | 2;
    const bool odd = lane & 1;
    const int m0r = warp * 16 + g;

    for (int kt = 0; kt < S_; kt += 32) {
        __syncthreads();
#pragma unroll
        for (int i = 0; i < 9; i++) {
            const int id = tid + i * 128;
            const int r = id / 36, d = (id % 36) * 2;
            *(uint2*)&sK[r * 76 + d] = *(const uint2*)&Kg[(size_t)(kt + r) * D_ + d];
        }
#pragma unroll
        for (int i = 0; i < 9; i++) {
            const int id = tid + i * 128;
            const int d = id >> 4, c = (id & 15) * 2;
            *(uint2*)&sVt[d * 40 + c] = *(const uint2*)&Vg[(size_t)d * S_ + kt + c];
        }
        __syncthreads();

        float Sc[4][4];
#pragma unroll
        for (int i = 0; i < 4; i++)
#pragma unroll
            for (int j = 0; j < 4; j++) Sc[i][j] = 0.0f;
#pragma unroll
        for (int ks = 0; ks < 9; ks++) {
            const int kk = ks * 8 + tg;
            const uint32_t a0 = sQ[m0r * 76 + kk];
            const uint32_t a1 = sQ[(m0r + 8) * 76 + kk];
            const uint32_t a2 = sQ[m0r * 76 + kk + 4];
            const uint32_t a3 = sQ[(m0r + 8) * 76 + kk + 4];
#pragma unroll
            for (int na = 0; na < 4; na++) {
                const uint32_t b0 = sK[(na * 8 + g) * 76 + kk];
                const uint32_t b1 = sK[(na * 8 + g) * 76 + kk + 4];
                mma_tf32(Sc[na], a0, a1, a2, a3, b0, b1);
            }
        }

        float mx0 = -3.0e38f, mx1 = -3.0e38f;
#pragma unroll
        for (int na = 0; na < 4; na++) {
            mx0 = fmaxf(mx0, fmaxf(Sc[na][0], Sc[na][1]));
            mx1 = fmaxf(mx1, fmaxf(Sc[na][2], Sc[na][3]));
        }
        mx0 = fmaxf(mx0, __shfl_xor_sync(0xffffffffu, mx0, 1));
        mx0 = fmaxf(mx0, __shfl_xor_sync(0xffffffffu, mx0, 2));
        mx1 = fmaxf(mx1, __shfl_xor_sync(0xffffffffu, mx1, 1));
        mx1 = fmaxf(mx1, __shfl_xor_sync(0xffffffffu, mx1, 2));

        const float nm0 = fmaxf(m0, mx0), nm1 = fmaxf(m1, mx1);
        const float al0 = __expf(m0 - nm0), al1 = __expf(m1 - nm1);
        float s0 = 0.0f, s1 = 0.0f;
#pragma unroll
        for (int na = 0; na < 4; na++) {
            Sc[na][0] = __expf(Sc[na][0] - nm0);
            Sc[na][1] = __expf(Sc[na][1] - nm0);
            Sc[na][2] = __expf(Sc[na][2] - nm1);
            Sc[na][3] = __expf(Sc[na][3] - nm1);
            s0 += Sc[na][0] + Sc[na][1];
            s1 += Sc[na][2] + Sc[na][3];
        }
        s0 += __shfl_xor_sync(0xffffffffu, s0, 1);
        s0 += __shfl_xor_sync(0xffffffffu, s0, 2);
        s1 += __shfl_xor_sync(0xffffffffu, s1, 1);
        s1 += __shfl_xor_sync(0xffffffffu, s1, 2);
        l0 = l0 * al0 + s0;
        l1 = l1 * al1 + s1;
        m0 = nm0; m1 = nm1;
#pragma unroll
        for (int na = 0; na < 9; na++) {
            O[na][0] *= al0; O[na][1] *= al0;
            O[na][2] *= al1; O[na][3] *= al1;
        }

#pragma unroll
        for (int ks = 0; ks < 4; ks++) {
            const float y00 = __shfl_sync(0xffffffffu, Sc[ks][0], srcLo);
            const float y01 = __shfl_sync(0xffffffffu, Sc[ks][1], srcLo);
            const float y02 = __shfl_sync(0xffffffffu, Sc[ks][0], srcHi);
            const float y03 = __shfl_sync(0xffffffffu, Sc[ks][1], srcHi);
            const float y10 = __shfl_sync(0xffffffffu, Sc[ks][2], srcLo);
            const float y11 = __shfl_sync(0xffffffffu, Sc[ks][3], srcLo);
            const float y12 = __shfl_sync(0xffffffffu, Sc[ks][2], srcHi);
            const float y13 = __shfl_sync(0xffffffffu, Sc[ks][3], srcHi);
            const uint32_t a0 = f2tf(odd ? y01 : y00);
            const uint32_t a2 = f2tf(odd ? y03 : y02);
            const uint32_t a1 = f2tf(odd ? y11 : y10);
            const uint32_t a3 = f2tf(odd ? y13 : y12);
            const int kk = ks * 8 + tg;
#pragma unroll
            for (int na = 0; na < 9; na++) {
                const uint32_t b0 = sVt[(na * 8 + g) * 40 + kk];
                const uint32_t b1 = sVt[(na * 8 + g) * 40 + kk + 4];
                mma_tf32(O[na], a0, a1, a2, a3, b0, b1);
            }
        }
    }

    const float i0 = 1.0f / l0, i1 = 1.0f / l1;
    const int r0 = qt * 64 + warp * 16 + g;
    uint32_t* out0 = g_Atf + (size_t)(b * S_ + r0) * E_ + h * D_;
    uint32_t* out1 = g_Atf + (size_t)(b * S_ + r0 + 8) * E_ + h * D_;
#pragma unroll
    for (int na = 0; na < 9; na++) {
        const int c = na * 8 + 2 * tg;
        *(uint2*)&out0[c] = make_uint2(f2tf(O[na][0] * i0), f2tf(O[na][1] * i0));
        *(uint2*)&out1[c] = make_uint2(f2tf(O[na][2] * i1), f2tf(O[na][3] * i1));
    }
}

// ---------------------------------------------------------------------------
// Output projection: A = g_Atf (tf32, no cvt), B = out_w fp32 (cvt at STS).
// grid (1152/128, 8192/128), 256 threads.
// ---------------------------------------------------------------------------
__global__ void __launch_bounds__(256) out_gemm(
    const float* __restrict__ W, const float* __restrict__ bias,
    float* __restrict__ outp)
{
    const int rowBase = blockIdx.y * 128;
    const int colBase = blockIdx.x * 128;

    __shared__ __align__(16) uint32_t sA[2][16 * 136];
    __shared__ __align__(16) uint32_t sB[2][16 * 136];

    const int tid  = threadIdx.x;
    const int lane = tid & 31, warp = tid >> 5;
    const int wm = warp >> 2, wn = warp & 3;
    const int g = lane >> 2, tg = lane & 3;

    const int rowA = tid >> 2;
    const int kcA  = (tid & 3) * 4;
    const int krB  = tid >> 5;
    const int ncB  = (tid & 31) * 4;

    float acc[4][4][4];
#pragma unroll
    for (int i = 0; i < 4; i++)
#pragma unroll
        for (int j = 0; j < 4; j++)
#pragma unroll
            for (int l = 0; l < 4; l++) acc[i][j][l] = 0.0f;

    uint4 a0v, a1v;
    float4 b0v, b1v;
    a0v = *(const uint4*)&g_Atf[(size_t)(rowBase + rowA) * E_ + kcA];
    a1v = *(const uint4*)&g_Atf[(size_t)(rowBase + rowA + 64) * E_ + kcA];
    b0v = *(const float4*)&W[(size_t)krB * E_ + colBase + ncB];
    b1v = *(const float4*)&W[(size_t)(krB + 8) * E_ + colBase + ncB];
    {
        uint32_t* A  = sA[0];
        uint32_t* Bs = sB[0];
        A[(kcA + 0) * 136 + rowA] = a0v.x;
        A[(kcA + 1) * 136 + rowA] = a0v.y;
        A[(kcA + 2) * 136 + rowA] = a0v.z;
        A[(kcA + 3) * 136 + rowA] = a0v.w;
        A[(kcA + 0) * 136 + rowA + 64] = a1v.x;
        A[(kcA + 1) * 136 + rowA + 64] = a1v.y;
        A[(kcA + 2) * 136 + rowA + 64] = a1v.z;
        A[(kcA + 3) * 136 + rowA + 64] = a1v.w;
        *(uint4*)&Bs[krB * 136 + ncB] =
            make_uint4(f2tf(b0v.x), f2tf(b0v.y), f2tf(b0v.z), f2tf(b0v.w));
        *(uint4*)&Bs[(krB + 8) * 136 + ncB] =
            make_uint4(f2tf(b1v.x), f2tf(b1v.y), f2tf(b1v.z), f2tf(b1v.w));
    }
    __syncthreads();

    int stage = 0;
    for (int kt = 0; kt < E_; kt += 16) {
        if (kt + 16 < E_) {
            a0v = *(const uint4*)&g_Atf[(size_t)(rowBase + rowA) * E_ + kt + 16 + kcA];
            a1v = *(const uint4*)&g_Atf[(size_t)(rowBase + rowA + 64) * E_ + kt + 16 + kcA];
            b0v = *(const float4*)&W[(size_t)(kt + 16 + krB) * E_ + colBase + ncB];
            b1v = *(const float4*)&W[(size_t)(kt + 16 + krB + 8) * E_ + colBase + ncB];
        }
        const uint32_t* A  = sA[stage];
        const uint32_t* Bv = sB[stage];
#pragma unroll
        for (int ks = 0; ks < 2; ks++) {
            uint32_t af[4][4], bf[4][2];
            const int kk = ks * 8 + tg;
#pragma unroll
            for (int ma = 0; ma < 4; ma++) {
                const int m0 = wm * 64 + ma * 16 + g;
                af[ma][0] = A[kk * 136 + m0];
                af[ma][1] = A[kk * 136 + m0 + 8];
                af[ma][2] = A[(kk + 4) * 136 + m0];
                af[ma][3] = A[(kk + 4) * 136 + m0 + 8];
            }
#pragma unroll
            for (int na = 0; na < 4; na++) {
                const int n0 = wn * 32 + na * 8 + g;
                bf[na][0] = Bv[kk * 136 + n0];
                bf[na][1] = Bv[(kk + 4) * 136 + n0];
            }
#pragma unroll
            for (int ma = 0; ma < 4; ma++)
#pragma unroll
                for (int na = 0; na < 4; na++)
                    mma_tf32(acc[ma][na], af[ma][0], af[ma][1], af[ma][2],
                             af[ma][3], bf[na][0], bf[na][1]);
        }
        if (kt + 16 < E_) {
            uint32_t* A2  = sA[stage ^ 1];
            uint32_t* Bs2 = sB[stage ^ 1];
            A2[(kcA + 0) * 136 + rowA] = a0v.x;
            A2[(kcA + 1) * 136 + rowA] = a0v.y;
            A2[(kcA + 2) * 136 + rowA] = a0v.z;
            A2[(kcA + 3) * 136 + rowA] = a0v.w;
            A2[(kcA + 0) * 136 + rowA + 64] = a1v.x;
            A2[(kcA + 1) * 136 + rowA + 64] = a1v.y;
            A2[(kcA + 2) * 136 + rowA + 64] = a1v.z;
            A2[(kcA + 3) * 136 + rowA + 64] = a1v.w;
            *(uint4*)&Bs2[krB * 136 + ncB] =
                make_uint4(f2tf(b0v.x), f2tf(b0v.y), f2tf(b0v.z), f2tf(b0v.w));
            *(uint4*)&Bs2[(krB + 8) * 136 + ncB] =
                make_uint4(f2tf(b1v.x), f2tf(b1v.y), f2tf(b1v.z), f2tf(b1v.w));
        }
        __syncthreads();
        stage ^= 1;
    }

#pragma unroll
    for (int ma = 0; ma < 4; ma++) {
#pragma unroll
        for (int na = 0; na < 4; na++) {
            const int c = colBase + wn * 32 + na * 8 + 2 * tg;
            const float bx = bias[c];
            const float by = bias[c + 1];
#pragma unroll
            for (int half = 0; half < 2; half++) {
                const int r = rowBase + wm * 64 + ma * 16 + g + half * 8;
                float2 ov;
                ov.x = acc[ma][na][half * 2 + 0] + bx;
                ov.y = acc[ma][na][half * 2 + 1] + by;
                *(float2*)&outp[(size_t)r * E_ + c] = ov;
            }
        }
    }
}

// ---------------------------------------------------------------------------
extern "C" void kernel_launch(void* const* d_in, const int* in_sizes, int n_in,
                              void* d_out, int out_size)
{
    const float* q    = (const float*)d_in[0];
    const float* k    = (const float*)d_in[1];
    const float* v    = (const float*)d_in[2];
    const float* W    = (const float*)d_in[3];
    const float* bias = (const float*)d_in[4];
    const float* ow   = (const float*)d_in[5];
    const float* ob   = (const float*)d_in[6];
    float* out = (float*)d_out;

    qkv_gemm<<<dim3(E_ / 128, NROW / 128, 3), 256>>>(q, k, v, W, bias);

    attn_kernel<<<dim3(S_ / 64, H_, B_), 128>>>();

    out_gemm<<<dim3(E_ / 128, NROW / 128, 1), 256>>>(ow, ob, out);
}

// round 9
// speedup vs baseline: 4.2762x; 1.0295x over previous
#include <cuda_runtime.h>
#include <cstdint>

#define B_   8
#define S_   1024
#define E_   1152
#define H_   16
#define D_   72
#define NROW (B_ * S_)
#define W3E  (3 * E_)
#define CH_  (B_ * H_ * S_ * D_)   // 9437184 words = 36 MiB

// ------- device scratch: single 144 MiB pool (R8-proven budget), aliased -------
// [0,CH)      : Qs (tf32, pre-scaled by 72^-0.5*log2e)  -> later owtf (out_w tf32)
// [CH,2CH)    : Ktf
// [2CH,3CH)   : Vt (transposed [b,h,d,s])
// [3CH,4CH)   : Wtf (in_proj tf32) during qkv -> Atf (attention out) after
__device__ uint32_t g_pool[4ull * CH_];

#define P_QS  (g_pool)
#define P_K   (g_pool + (size_t)CH_)
#define P_V   (g_pool + 2ull * CH_)
#define P_AW  (g_pool + 3ull * CH_)
#define P_OWT (g_pool)

// ---------------- helpers ----------------
__device__ __forceinline__ uint32_t f2tf(float f) {
    uint32_t u;
    asm("cvt.rna.tf32.f32 %0, %1;" : "=r"(u) : "f"(f));
    return u;
}
__device__ __forceinline__ float ex2f(float x) {
    float y;
    asm("ex2.approx.f32 %0, %1;" : "=f"(y) : "f"(x));
    return y;
}
__device__ __forceinline__ uint32_t smem_u32(const void* p) {
    uint32_t a;
    asm("{ .reg .u64 t; cvta.to.shared.u64 t, %1; cvt.u32.u64 %0, t; }"
        : "=r"(a) : "l"(p));
    return a;
}
__device__ __forceinline__ void cpa16(uint32_t s, const void* g) {
    asm volatile("cp.async.cg.shared.global [%0], [%1], 16;"
                 :: "r"(s), "l"(g) : "memory");
}
__device__ __forceinline__ void mma_tf32(float (&c)[4],
    uint32_t a0, uint32_t a1, uint32_t a2, uint32_t a3,
    uint32_t b0, uint32_t b1)
{
    asm volatile(
        "mma.sync.aligned.m16n8k8.row.col.f32.tf32.tf32.f32 "
        "{%0,%1,%2,%3}, {%4,%5,%6,%7}, {%8,%9}, {%0,%1,%2,%3};\n"
        : "+f"(c[0]), "+f"(c[1]), "+f"(c[2]), "+f"(c[3])
        : "r"(a0), "r"(a1), "r"(a2), "r"(a3), "r"(b0), "r"(b1));
}

// ---------------------------------------------------------------------------
// Elementwise fp32 -> tf32 into pool at word offset
// ---------------------------------------------------------------------------
__global__ void cvt_arr(const float4* __restrict__ src, size_t dst_off, int n4) {
    uint4* dst = (uint4*)(g_pool + dst_off);
    for (int i = blockIdx.x * blockDim.x + threadIdx.x; i < n4;
         i += gridDim.x * blockDim.x) {
        float4 w = src[i];
        dst[i] = make_uint4(f2tf(w.x), f2tf(w.y), f2tf(w.z), f2tf(w.w));
    }
}

// ---------------------------------------------------------------------------
// QKV GEMM: A fp32 (reg-staged, cvt at STS.128, [m][k+4] layout),
//           B tf32 via cp.async 2-stage ([k][n] 136-stride layout).
// Epilogue -> Qs (scaled tf32), Ktf, Vt (transposed).
// grid (1152/128, 8192/128, 3), 256 threads (8 warps as 2m x 4n).
// ---------------------------------------------------------------------------
#define TQK 72   // k-tiles of 16

__global__ void __launch_bounds__(256) qkv_gemm(
    const float* __restrict__ q, const float* __restrict__ k,
    const float* __restrict__ v, const float* __restrict__ bias)
{
    const int z = blockIdx.z;
    const float* X = (z == 0) ? q : (z == 1) ? k : v;
    const uint32_t* Wt = P_AW;   // tf32 weights [k][3E]

    const int rowBase = blockIdx.y * 128;
    const int colBase = blockIdx.x * 128;
    const int wcol0   = z * E_ + colBase;

    __shared__ __align__(16) uint32_t sA[2][128 * 20];
    __shared__ __align__(16) uint32_t sB[2][16 * 136];

    const int tid  = threadIdx.x;
    const int lane = tid & 31, warp = tid >> 5;
    const int wm = warp >> 2, wn = warp & 3;
    const int g = lane >> 2, tg = lane & 3;

    const int rowA = tid >> 1;          // 0..127
    const int kcA  = (tid & 1) * 8;     // word col 0 or 8
    const int krB  = tid >> 5;          // 0..7 (and +8)
    const int ncB  = (tid & 31) * 4;

    const uint32_t sB0 = smem_u32(&sB[0][0]);
    const uint32_t sB1 = smem_u32(&sB[1][0]);

    float acc[4][4][4];
#pragma unroll
    for (int i = 0; i < 4; i++)
#pragma unroll
        for (int j = 0; j < 4; j++)
#pragma unroll
            for (int l = 0; l < 4; l++) acc[i][j][l] = 0.0f;

    float4 a0v, a1v;

    // ---- prologue: tile 0 ----
    a0v = *(const float4*)&X[(size_t)(rowBase + rowA) * E_ + kcA];
    a1v = *(const float4*)&X[(size_t)(rowBase + rowA) * E_ + kcA + 4];
    *(uint4*)&sA[0][rowA * 20 + kcA] =
        make_uint4(f2tf(a0v.x), f2tf(a0v.y), f2tf(a0v.z), f2tf(a0v.w));
    *(uint4*)&sA[0][rowA * 20 + kcA + 4] =
        make_uint4(f2tf(a1v.x), f2tf(a1v.y), f2tf(a1v.z), f2tf(a1v.w));
    cpa16(sB0 + (krB * 136 + ncB) * 4, Wt + (size_t)krB * W3E + wcol0 + ncB);
    cpa16(sB0 + ((krB + 8) * 136 + ncB) * 4,
          Wt + (size_t)(krB + 8) * W3E + wcol0 + ncB);
    asm volatile("cp.async.commit_group;" ::: "memory");

    for (int t = 0; t < TQK; t++) {
        const int kt = t * 16;
        if (t + 1 < TQK) {  // early A LDG for next tile
            a0v = *(const float4*)&X[(size_t)(rowBase + rowA) * E_ + kt + 16 + kcA];
            a1v = *(const float4*)&X[(size_t)(rowBase + rowA) * E_ + kt + 16 + kcA + 4];
        }
        asm volatile("cp.async.wait_group 0;" ::: "memory");
        __syncthreads();
        if (t + 1 < TQK) {
            const uint32_t dB = ((t + 1) & 1) ? sB1 : sB0;
            cpa16(dB + (krB * 136 + ncB) * 4,
                  Wt + (size_t)(kt + 16 + krB) * W3E + wcol0 + ncB);
            cpa16(dB + ((krB + 8) * 136 + ncB) * 4,
                  Wt + (size_t)(kt + 16 + krB + 8) * W3E + wcol0 + ncB);
            asm volatile("cp.async.commit_group;" ::: "memory");
        }

        const uint32_t* As = sA[t & 1];
        const uint32_t* Bv = sB[t & 1];
#pragma unroll
        for (int ks = 0; ks < 2; ks++) {
            const int kk = ks * 8 + tg;
            uint32_t af[4][4], bf[4][2];
#pragma unroll
            for (int ma = 0; ma < 4; ma++) {
                const int m0 = wm * 64 + ma * 16 + g;
                af[ma][0] = As[m0 * 20 + kk];
                af[ma][1] = As[(m0 + 8) * 20 + kk];
                af[ma][2] = As[m0 * 20 + kk + 4];
                af[ma][3] = As[(m0 + 8) * 20 + kk + 4];
            }
#pragma unroll
            for (int na = 0; na < 4; na++) {
                const int n0 = wn * 32 + na * 8 + g;
                bf[na][0] = Bv[kk * 136 + n0];
                bf[na][1] = Bv[(kk + 4) * 136 + n0];
            }
#pragma unroll
            for (int ma = 0; ma < 4; ma++)
#pragma unroll
                for (int na = 0; na < 4; na++)
                    mma_tf32(acc[ma][na], af[ma][0], af[ma][1], af[ma][2],
                             af[ma][3], bf[na][0], bf[na][1]);
        }

        if (t + 1 < TQK) {  // A store after MMA (LDG latency covered)
            uint32_t* A2 = sA[(t + 1) & 1];
            *(uint4*)&A2[rowA * 20 + kcA] =
                make_uint4(f2tf(a0v.x), f2tf(a0v.y), f2tf(a0v.z), f2tf(a0v.w));
            *(uint4*)&A2[rowA * 20 + kcA + 4] =
                make_uint4(f2tf(a1v.x), f2tf(a1v.y), f2tf(a1v.z), f2tf(a1v.w));
        }
    }

    // ---- epilogue: attention-ready tf32 operands ----
    // Q scale folds log2(e) for the exp2-domain softmax.
    const float scale = 0.17002325737443355f;  // 72^-0.5 * log2(e)
#pragma unroll
    for (int ma = 0; ma < 4; ma++) {
#pragma unroll
        for (int na = 0; na < 4; na++) {
            const int c  = colBase + wn * 32 + na * 8 + 2 * tg;
            const float bx = bias[z * E_ + c];
            const float by = bias[z * E_ + c + 1];
            const int hh = c / D_;
            const int dd = c - hh * D_;
#pragma unroll
            for (int half = 0; half < 2; half++) {
                const int r = rowBase + wm * 64 + ma * 16 + g + half * 8;
                const int bb = r >> 10, ss = r & 1023;
                const float vx = acc[ma][na][half * 2 + 0] + bx;
                const float vy = acc[ma][na][half * 2 + 1] + by;
                if (z == 0) {
                    *(uint2*)&P_QS[((size_t)(bb * H_ + hh) * S_ + ss) * D_ + dd] =
                        make_uint2(f2tf(vx * scale), f2tf(vy * scale));
                } else if (z == 1) {
                    *(uint2*)&P_K[((size_t)(bb * H_ + hh) * S_ + ss) * D_ + dd] =
                        make_uint2(f2tf(vx), f2tf(vy));
                } else {
                    P_V[((size_t)(bb * H_ + hh) * D_ + dd) * S_ + ss]     = f2tf(vx);
                    P_V[((size_t)(bb * H_ + hh) * D_ + dd + 1) * S_ + ss] = f2tf(vy);
                }
            }
        }
    }
}

// ---------------------------------------------------------------------------
// Flash attention (exp2-domain softmax). grid (S/64, H, B), 128 threads.
// ---------------------------------------------------------------------------
__global__ void __launch_bounds__(128) attn_kernel()
{
    const int qt = blockIdx.x, h = blockIdx.y, b = blockIdx.z;
    const int tid = threadIdx.x;
    const int lane = tid & 31, warp = tid >> 5;
    const int g = lane >> 2, tg = lane & 3;

    __shared__ __align__(16) uint32_t sQ[64 * 76];
    __shared__ __align__(16) uint32_t sK[32 * 76];
    __shared__ __align__(16) uint32_t sVt[72 * 40];   // [d][key]

    const uint32_t* Qg = P_QS + ((size_t)(b * H_ + h) * S_ + qt * 64) * D_;
    const uint32_t* Kg = P_K  + (size_t)(b * H_ + h) * S_ * D_;
    const uint32_t* Vg = P_V  + (size_t)(b * H_ + h) * D_ * S_;

#pragma unroll
    for (int i = 0; i < 18; i++) {
        const int id = tid + i * 128;
        const int r = id / 36, d = (id % 36) * 2;
        *(uint2*)&sQ[r * 76 + d] = *(const uint2*)&Qg[r * D_ + d];
    }

    float O[9][4];
#pragma unroll
    for (int i = 0; i < 9; i++)
#pragma unroll
        for (int j = 0; j < 4; j++) O[i][j] = 0.0f;
    float m0 = -3.0e38f, m1 = -3.0e38f, l0 = 0.0f, l1 = 0.0f;

    const int srcLo = (lane & ~3) | (tg >> 1);
    const int srcHi = srcLo | 2;
    const bool odd = lane & 1;
    const int m0r = warp * 16 + g;

    for (int kt = 0; kt < S_; kt += 32) {
        __syncthreads();
#pragma unroll
        for (int i = 0; i < 9; i++) {
            const int id = tid + i * 128;
            const int r = id / 36, d = (id % 36) * 2;
            *(uint2*)&sK[r * 76 + d] = *(const uint2*)&Kg[(size_t)(kt + r) * D_ + d];
        }
#pragma unroll
        for (int i = 0; i < 9; i++) {
            const int id = tid + i * 128;
            const int d = id >> 4, c = (id & 15) * 2;
            *(uint2*)&sVt[d * 40 + c] = *(const uint2*)&Vg[(size_t)d * S_ + kt + c];
        }
        __syncthreads();

        float Sc[4][4];
#pragma unroll
        for (int i = 0; i < 4; i++)
#pragma unroll
            for (int j = 0; j < 4; j++) Sc[i][j] = 0.0f;
#pragma unroll
        for (int ks = 0; ks < 9; ks++) {
            const int kk = ks * 8 + tg;
            const uint32_t a0 = sQ[m0r * 76 + kk];
            const uint32_t a1 = sQ[(m0r + 8) * 76 + kk];
            const uint32_t a2 = sQ[m0r * 76 + kk + 4];
            const uint32_t a3 = sQ[(m0r + 8) * 76 + kk + 4];
#pragma unroll
            for (int na = 0; na < 4; na++) {
                const uint32_t b0 = sK[(na * 8 + g) * 76 + kk];
                const uint32_t b1 = sK[(na * 8 + g) * 76 + kk + 4];
                mma_tf32(Sc[na], a0, a1, a2, a3, b0, b1);
            }
        }

        float mx0 = -3.0e38f, mx1 = -3.0e38f;
#pragma unroll
        for (int na = 0; na < 4; na++) {
            mx0 = fmaxf(mx0, fmaxf(Sc[na][0], Sc[na][1]));
            mx1 = fmaxf(mx1, fmaxf(Sc[na][2], Sc[na][3]));
        }
        mx0 = fmaxf(mx0, __shfl_xor_sync(0xffffffffu, mx0, 1));
        mx0 = fmaxf(mx0, __shfl_xor_sync(0xffffffffu, mx0, 2));
        mx1 = fmaxf(mx1, __shfl_xor_sync(0xffffffffu, mx1, 1));
        mx1 = fmaxf(mx1, __shfl_xor_sync(0xffffffffu, mx1, 2));

        const float nm0 = fmaxf(m0, mx0), nm1 = fmaxf(m1, mx1);
        const float al0 = ex2f(m0 - nm0), al1 = ex2f(m1 - nm1);
        float s0 = 0.0f, s1 = 0.0f;
#pragma unroll
        for (int na = 0; na < 4; na++) {
            Sc[na][0] = ex2f(Sc[na][0] - nm0);
            Sc[na][1] = ex2f(Sc[na][1] - nm0);
            Sc[na][2] = ex2f(Sc[na][2] - nm1);
            Sc[na][3] = ex2f(Sc[na][3] - nm1);
            s0 += Sc[na][0] + Sc[na][1];
            s1 += Sc[na][2] + Sc[na][3];
        }
        s0 += __shfl_xor_sync(0xffffffffu, s0, 1);
        s0 += __shfl_xor_sync(0xffffffffu, s0, 2);
        s1 += __shfl_xor_sync(0xffffffffu, s1, 1);
        s1 += __shfl_xor_sync(0xffffffffu, s1, 2);
        l0 = l0 * al0 + s0;
        l1 = l1 * al1 + s1;
        m0 = nm0; m1 = nm1;
#pragma unroll
        for (int na = 0; na < 9; na++) {
            O[na][0] *= al0; O[na][1] *= al0;
            O[na][2] *= al1; O[na][3] *= al1;
        }

#pragma unroll
        for (int ks = 0; ks < 4; ks++) {
            const float y00 = __shfl_sync(0xffffffffu, Sc[ks][0], srcLo);
            const float y01 = __shfl_sync(0xffffffffu, Sc[ks][1], srcLo);
            const float y02 = __shfl_sync(0xffffffffu, Sc[ks][0], srcHi);
            const float y03 = __shfl_sync(0xffffffffu, Sc[ks][1], srcHi);
            const float y10 = __shfl_sync(0xffffffffu, Sc[ks][2], srcLo);
            const float y11 = __shfl_sync(0xffffffffu, Sc[ks][3], srcLo);
            const float y12 = __shfl_sync(0xffffffffu, Sc[ks][2], srcHi);
            const float y13 = __shfl_sync(0xffffffffu, Sc[ks][3], srcHi);
            const uint32_t a0 = f2tf(odd ? y01 : y00);
            const uint32_t a2 = f2tf(odd ? y03 : y02);
            const uint32_t a1 = f2tf(odd ? y11 : y10);
            const uint32_t a3 = f2tf(odd ? y13 : y12);
            const int kk = ks * 8 + tg;
#pragma unroll
            for (int na = 0; na < 9; na++) {
                const uint32_t b0 = sVt[(na * 8 + g) * 40 + kk];
                const uint32_t b1 = sVt[(na * 8 + g) * 40 + kk + 4];
                mma_tf32(O[na], a0, a1, a2, a3, b0, b1);
            }
        }
    }

    const float i0 = 1.0f / l0, i1 = 1.0f / l1;
    const int r0 = qt * 64 + warp * 16 + g;
    uint32_t* out0 = P_AW + (size_t)(b * S_ + r0) * E_ + h * D_;
    uint32_t* out1 = P_AW + (size_t)(b * S_ + r0 + 8) * E_ + h * D_;
#pragma unroll
    for (int na = 0; na < 9; na++) {
        const int c = na * 8 + 2 * tg;
        *(uint2*)&out0[c] = make_uint2(f2tf(O[na][0] * i0), f2tf(O[na][1] * i0));
        *(uint2*)&out1[c] = make_uint2(f2tf(O[na][2] * i1), f2tf(O[na][3] * i1));
    }
}

// ---------------------------------------------------------------------------
// Output projection: fully cp.async (A=Atf tf32, B=owtf tf32), zero cvt.
// grid (1152/128, 8192/128), 256 threads.
// ---------------------------------------------------------------------------
__global__ void __launch_bounds__(256) out_gemm(const float* __restrict__ bias,
                                                float* __restrict__ outp)
{
    const int rowBase = blockIdx.y * 128;
    const int colBase = blockIdx.x * 128;
    const uint32_t* At = P_AW;   // [row][k] tf32
    const uint32_t* Wt = P_OWT;  // [k][n] tf32

    __shared__ __align__(16) uint32_t sA[2][128 * 20];
    __shared__ __align__(16) uint32_t sB[2][16 * 136];

    const int tid  = threadIdx.x;
    const int lane = tid & 31, warp = tid >> 5;
    const int wm = warp >> 2, wn = warp & 3;
    const int g = lane >> 2, tg = lane & 3;

    const int rowA = tid >> 1;
    const int kcA  = (tid & 1) * 8;
    const int krB  = tid >> 5;
    const int ncB  = (tid & 31) * 4;

    const uint32_t sA0 = smem_u32(&sA[0][0]);
    const uint32_t sA1 = smem_u32(&sA[1][0]);
    const uint32_t sB0 = smem_u32(&sB[0][0]);
    const uint32_t sB1 = smem_u32(&sB[1][0]);

    float acc[4][4][4];
#pragma unroll
    for (int i = 0; i < 4; i++)
#pragma unroll
        for (int j = 0; j < 4; j++)
#pragma unroll
            for (int l = 0; l < 4; l++) acc[i][j][l] = 0.0f;

    // prologue tile 0
    cpa16(sA0 + (rowA * 20 + kcA) * 4, At + (size_t)(rowBase + rowA) * E_ + kcA);
    cpa16(sA0 + (rowA * 20 + kcA + 4) * 4,
          At + (size_t)(rowBase + rowA) * E_ + kcA + 4);
    cpa16(sB0 + (krB * 136 + ncB) * 4, Wt + (size_t)krB * E_ + colBase + ncB);
    cpa16(sB0 + ((krB + 8) * 136 + ncB) * 4,
          Wt + (size_t)(krB + 8) * E_ + colBase + ncB);
    asm volatile("cp.async.commit_group;" ::: "memory");

    for (int t = 0; t < TQK; t++) {
        const int kt = t * 16;
        asm volatile("cp.async.wait_group 0;" ::: "memory");
        __syncthreads();
        if (t + 1 < TQK) {
            const uint32_t dA = ((t + 1) & 1) ? sA1 : sA0;
            const uint32_t dB = ((t + 1) & 1) ? sB1 : sB0;
            cpa16(dA + (rowA * 20 + kcA) * 4,
                  At + (size_t)(rowBase + rowA) * E_ + kt + 16 + kcA);
            cpa16(dA + (rowA * 20 + kcA + 4) * 4,
                  At + (size_t)(rowBase + rowA) * E_ + kt + 16 + kcA + 4);
            cpa16(dB + (krB * 136 + ncB) * 4,
                  Wt + (size_t)(kt + 16 + krB) * E_ + colBase + ncB);
            cpa16(dB + ((krB + 8) * 136 + ncB) * 4,
                  Wt + (size_t)(kt + 16 + krB + 8) * E_ + colBase + ncB);
            asm volatile("cp.async.commit_group;" ::: "memory");
        }

        const uint32_t* As = sA[t & 1];
        const uint32_t* Bv = sB[t & 1];
#pragma unroll
        for (int ks = 0; ks < 2; ks++) {
            const int kk = ks * 8 + tg;
            uint32_t af[4][4], bf[4][2];
#pragma unroll
            for (int ma = 0; ma < 4; ma++) {
                const int m0 = wm * 64 + ma * 16 + g;
                af[ma][0] = As[m0 * 20 + kk];
                af[ma][1] = As[(m0 + 8) * 20 + kk];
                af[ma][2] = As[m0 * 20 + kk + 4];
                af[ma][3] = As[(m0 + 8) * 20 + kk + 4];
            }
#pragma unroll
            for (int na = 0; na < 4; na++) {
                const int n0 = wn * 32 + na * 8 + g;
                bf[na][0] = Bv[kk * 136 + n0];
                bf[na][1] = Bv[(kk + 4) * 136 + n0];
            }
#pragma unroll
            for (int ma = 0; ma < 4; ma++)
#pragma unroll
                for (int na = 0; na < 4; na++)
                    mma_tf32(acc[ma][na], af[ma][0], af[ma][1], af[ma][2],
                             af[ma][3], bf[na][0], bf[na][1]);
        }
    }

#pragma unroll
    for (int ma = 0; ma < 4; ma++) {
#pragma unroll
        for (int na = 0; na < 4; na++) {
            const int c = colBase + wn * 32 + na * 8 + 2 * tg;
            const float bx = bias[c];
            const float by = bias[c + 1];
#pragma unroll
            for (int half = 0; half < 2; half++) {
                const int r = rowBase + wm * 64 + ma * 16 + g + half * 8;
                float2 ov;
                ov.x = acc[ma][na][half * 2 + 0] + bx;
                ov.y = acc[ma][na][half * 2 + 1] + by;
                *(float2*)&outp[(size_t)r * E_ + c] = ov;
            }
        }
    }
}

// ---------------------------------------------------------------------------
extern "C" void kernel_launch(void* const* d_in, const int* in_sizes, int n_in,
                              void* d_out, int out_size)
{
    const float* q    = (const float*)d_in[0];
    const float* k    = (const float*)d_in[1];
    const float* v    = (const float*)d_in[2];
    const float* W    = (const float*)d_in[3];
    const float* bias = (const float*)d_in[4];
    const float* ow   = (const float*)d_in[5];
    const float* ob   = (const float*)d_in[6];
    float* out = (float*)d_out;

    // in_proj W -> tf32 at P_AW (region later becomes Atf)
    cvt_arr<<<1024, 256>>>((const float4*)W, 3ull * CH_, E_ * W3E / 4);

    qkv_gemm<<<dim3(E_ / 128, NROW / 128, 3), 256>>>(q, k, v, bias);

    attn_kernel<<<dim3(S_ / 64, H_, B_), 128>>>();

    // out_w -> tf32 at P_OWT (overwrites dead Qs region)
    cvt_arr<<<512, 256>>>((const float4*)ow, 0, E_ * E_ / 4);

    out_gemm<<<dim3(E_ / 128, NROW / 128, 1), 256>>>(ob, out);
}

// round 11
// speedup vs baseline: 4.5619x; 1.0668x over previous
#include <cuda_runtime.h>
#include <cstdint>

#define B_   8
#define S_   1024
#define E_   1152
#define H_   16
#define D_   72
#define NROW (B_ * S_)
#define W3E  (3 * E_)
#define CH_  (B_ * H_ * S_ * D_)   // 9437184 words = 36 MiB

// ------- device scratch: single 144 MiB pool (proven budget), aliased -------
__device__ uint32_t g_pool[4ull * CH_];
#define P_QS  (g_pool)
#define P_K   (g_pool + (size_t)CH_)
#define P_V   (g_pool + 2ull * CH_)
#define P_AW  (g_pool + 3ull * CH_)
#define P_OWT (g_pool)

// ---------------- helpers ----------------
__device__ __forceinline__ uint32_t f2tf(float f) {
    uint32_t u;
    asm("cvt.rna.tf32.f32 %0, %1;" : "=r"(u) : "f"(f));
    return u;
}
__device__ __forceinline__ float ex2f(float x) {
    float y;
    asm("ex2.approx.f32 %0, %1;" : "=f"(y) : "f"(x));
    return y;
}
__device__ __forceinline__ uint32_t smem_u32(const void* p) {
    uint32_t a;
    asm("{ .reg .u64 t; cvta.to.shared.u64 t, %1; cvt.u32.u64 %0, t; }"
        : "=r"(a) : "l"(p));
    return a;
}
__device__ __forceinline__ void cpa16(uint32_t s, const void* g) {
    asm volatile("cp.async.cg.shared.global [%0], [%1], 16;"
                 :: "r"(s), "l"(g) : "memory");
}
__device__ __forceinline__ void mma_tf32(float (&c)[4],
    uint32_t a0, uint32_t a1, uint32_t a2, uint32_t a3,
    uint32_t b0, uint32_t b1)
{
    asm volatile(
        "mma.sync.aligned.m16n8k8.row.col.f32.tf32.tf32.f32 "
        "{%0,%1,%2,%3}, {%4,%5,%6,%7}, {%8,%9}, {%0,%1,%2,%3};\n"
        : "+f"(c[0]), "+f"(c[1]), "+f"(c[2]), "+f"(c[3])
        : "r"(a0), "r"(a1), "r"(a2), "r"(a3), "r"(b0), "r"(b1));
}

// ---------------------------------------------------------------------------
// Elementwise fp32 -> tf32 into pool at word offset
// ---------------------------------------------------------------------------
__global__ void cvt_arr(const float4* __restrict__ src, size_t dst_off, int n4) {
    uint4* dst = (uint4*)(g_pool + dst_off);
    for (int i = blockIdx.x * blockDim.x + threadIdx.x; i < n4;
         i += gridDim.x * blockDim.x) {
        float4 w = src[i];
        dst[i] = make_uint4(f2tf(w.x), f2tf(w.y), f2tf(w.z), f2tf(w.w));
    }
}

// ---------------------------------------------------------------------------
// QKV GEMM: A fp32 reg-staged (cvt at STS.128), B tf32 via 3-stage cp.async.
// Epilogue -> Qs (scaled tf32), Ktf, Vt (transposed).
// grid (1152/128, 8192/128, 3), 256 threads (8 warps as 2m x 4n).
// ---------------------------------------------------------------------------
#define TQK 72   // k-tiles of 16

__global__ void __launch_bounds__(256) qkv_gemm(
    const float* __restrict__ q, const float* __restrict__ k,
    const float* __restrict__ v, const float* __restrict__ bias)
{
    const int z = blockIdx.z;
    const float* X = (z == 0) ? q : (z == 1) ? k : v;
    const uint32_t* Wt = P_AW;   // tf32 weights [k][3E]

    const int rowBase = blockIdx.y * 128;
    const int colBase = blockIdx.x * 128;
    const int wcol0   = z * E_ + colBase;

    __shared__ __align__(16) uint32_t sA[2][128 * 20];
    __shared__ __align__(16) uint32_t sB[3][16 * 136];

    const int tid  = threadIdx.x;
    const int lane = tid & 31, warp = tid >> 5;
    const int wm = warp >> 2, wn = warp & 3;
    const int g = lane >> 2, tg = lane & 3;

    const int rowA = tid >> 1;          // 0..127
    const int kcA  = (tid & 1) * 8;     // word col 0 or 8
    const int krB  = tid >> 5;          // 0..7 (and +8)
    const int ncB  = (tid & 31) * 4;

    const uint32_t sBb = smem_u32(&sB[0][0]);

    float acc[4][4][4];
#pragma unroll
    for (int i = 0; i < 4; i++)
#pragma unroll
        for (int j = 0; j < 4; j++)
#pragma unroll
            for (int l = 0; l < 4; l++) acc[i][j][l] = 0.0f;

    float4 a0v, a1v;

    auto loadB = [&](int t) {
        const uint32_t dB = sBb + (uint32_t)(t % 3) * (16 * 136 * 4);
        cpa16(dB + (krB * 136 + ncB) * 4,
              Wt + (size_t)(t * 16 + krB) * W3E + wcol0 + ncB);
        cpa16(dB + ((krB + 8) * 136 + ncB) * 4,
              Wt + (size_t)(t * 16 + krB + 8) * W3E + wcol0 + ncB);
        asm volatile("cp.async.commit_group;" ::: "memory");
    };

    // ---- prologue ----
    a0v = *(const float4*)&X[(size_t)(rowBase + rowA) * E_ + kcA];
    a1v = *(const float4*)&X[(size_t)(rowBase + rowA) * E_ + kcA + 4];
    *(uint4*)&sA[0][rowA * 20 + kcA] =
        make_uint4(f2tf(a0v.x), f2tf(a0v.y), f2tf(a0v.z), f2tf(a0v.w));
    *(uint4*)&sA[0][rowA * 20 + kcA + 4] =
        make_uint4(f2tf(a1v.x), f2tf(a1v.y), f2tf(a1v.z), f2tf(a1v.w));
    loadB(0);
    loadB(1);

    for (int t = 0; t < TQK; t++) {
        const int kt = t * 16;
        if (t + 1 < TQK) {  // early A LDG for next tile
            a0v = *(const float4*)&X[(size_t)(rowBase + rowA) * E_ + kt + 16 + kcA];
            a1v = *(const float4*)&X[(size_t)(rowBase + rowA) * E_ + kt + 16 + kcA + 4];
        }
        if (t + 1 < TQK)
            asm volatile("cp.async.wait_group 1;" ::: "memory");
        else
            asm volatile("cp.async.wait_group 0;" ::: "memory");
        __syncthreads();
        if (t + 2 < TQK) loadB(t + 2);

        const uint32_t* As = sA[t & 1];
        const uint32_t* Bv = sB[t % 3];
#pragma unroll
        for (int ks = 0; ks < 2; ks++) {
            const int kk = ks * 8 + tg;
            uint32_t af[4][4], bf[4][2];
#pragma unroll
            for (int ma = 0; ma < 4; ma++) {
                const int m0 = wm * 64 + ma * 16 + g;
                af[ma][0] = As[m0 * 20 + kk];
                af[ma][1] = As[(m0 + 8) * 20 + kk];
                af[ma][2] = As[m0 * 20 + kk + 4];
                af[ma][3] = As[(m0 + 8) * 20 + kk + 4];
            }
#pragma unroll
            for (int na = 0; na < 4; na++) {
                const int n0 = wn * 32 + na * 8 + g;
                bf[na][0] = Bv[kk * 136 + n0];
                bf[na][1] = Bv[(kk + 4) * 136 + n0];
            }
#pragma unroll
            for (int ma = 0; ma < 4; ma++)
#pragma unroll
                for (int na = 0; na < 4; na++)
                    mma_tf32(acc[ma][na], af[ma][0], af[ma][1], af[ma][2],
                             af[ma][3], bf[na][0], bf[na][1]);
        }

        if (t + 1 < TQK) {  // A store after MMA (LDG latency covered)
            uint32_t* A2 = sA[(t + 1) & 1];
            *(uint4*)&A2[rowA * 20 + kcA] =
                make_uint4(f2tf(a0v.x), f2tf(a0v.y), f2tf(a0v.z), f2tf(a0v.w));
            *(uint4*)&A2[rowA * 20 + kcA + 4] =
                make_uint4(f2tf(a1v.x), f2tf(a1v.y), f2tf(a1v.z), f2tf(a1v.w));
        }
    }

    // ---- epilogue: attention-ready tf32 operands (Q folds log2e) ----
    const float scale = 0.17002325737443355f;  // 72^-0.5 * log2(e)
#pragma unroll
    for (int ma = 0; ma < 4; ma++) {
#pragma unroll
        for (int na = 0; na < 4; na++) {
            const int c  = colBase + wn * 32 + na * 8 + 2 * tg;
            const float bx = bias[z * E_ + c];
            const float by = bias[z * E_ + c + 1];
            const int hh = c / D_;
            const int dd = c - hh * D_;
#pragma unroll
            for (int half = 0; half < 2; half++) {
                const int r = rowBase + wm * 64 + ma * 16 + g + half * 8;
                const int bb = r >> 10, ss = r & 1023;
                const float vx = acc[ma][na][half * 2 + 0] + bx;
                const float vy = acc[ma][na][half * 2 + 1] + by;
                if (z == 0) {
                    *(uint2*)&P_QS[((size_t)(bb * H_ + hh) * S_ + ss) * D_ + dd] =
                        make_uint2(f2tf(vx * scale), f2tf(vy * scale));
                } else if (z == 1) {
                    *(uint2*)&P_K[((size_t)(bb * H_ + hh) * S_ + ss) * D_ + dd] =
                        make_uint2(f2tf(vx), f2tf(vy));
                } else {
                    P_V[((size_t)(bb * H_ + hh) * D_ + dd) * S_ + ss]     = f2tf(vx);
                    P_V[((size_t)(bb * H_ + hh) * D_ + dd + 1) * S_ + ss] = f2tf(vy);
                }
            }
        }
    }
}

// ---------------------------------------------------------------------------
// Flash attention: cp.async double-buffered K/V, exp2-domain softmax.
// Dynamic smem: sQ 64x76 | sK 2x32x76 | sVt 2x72x40 = 61952 B.
// grid (S/64, H, B), 128 threads.
// ---------------------------------------------------------------------------
__global__ void __launch_bounds__(128) attn_kernel()
{
    extern __shared__ uint32_t smdyn[];
    uint32_t* sQ  = smdyn;            // 4864 words
    uint32_t* sK  = smdyn + 4864;     // 2 x 2432
    uint32_t* sVt = smdyn + 9728;     // 2 x 2880

    const int qt = blockIdx.x, h = blockIdx.y, b = blockIdx.z;
    const int tid = threadIdx.x;
    const int lane = tid & 31, warp = tid >> 5;
    const int g = lane >> 2, tg = lane & 3;

    const uint32_t sQb = smem_u32(sQ);
    const uint32_t sKb = smem_u32(sK);
    const uint32_t sVb = smem_u32(sVt);

    const uint32_t* Qg = P_QS + ((size_t)(b * H_ + h) * S_ + qt * 64) * D_;
    const uint32_t* Kg = P_K  + (size_t)(b * H_ + h) * S_ * D_;
    const uint32_t* Vg = P_V  + (size_t)(b * H_ + h) * D_ * S_;

    auto load_tile = [&](int t, int buf) {
        const int kt = t * 32;
        const uint32_t dK = sKb + (uint32_t)buf * (2432 * 4);
        const uint32_t dV = sVb + (uint32_t)buf * (2880 * 4);
#pragma unroll
        for (int j = 0; j < 5; j++) {
            const int idx = j * 128 + tid;
            if (idx < 576) {
                const int r = idx / 18, c = (idx % 18) * 4;
                cpa16(dK + (r * 76 + c) * 4, Kg + (size_t)(kt + r) * D_ + c);
            }
        }
#pragma unroll
        for (int j = 0; j < 5; j++) {
            const int idx = j * 128 + tid;
            if (idx < 576) {
                const int d = idx >> 3, c = (idx & 7) * 4;
                cpa16(dV + (d * 40 + c) * 4, Vg + (size_t)d * S_ + kt + c);
            }
        }
        asm volatile("cp.async.commit_group;" ::: "memory");
    };

    // prologue: Q (64x72 = 1152 chunks of 16B; 9*128 exactly) + tiles 0,1
#pragma unroll
    for (int j = 0; j < 9; j++) {
        const int idx = j * 128 + tid;
        const int r = idx / 18, c = (idx % 18) * 4;
        cpa16(sQb + (r * 76 + c) * 4, Qg + (size_t)r * D_ + c);
    }
    load_tile(0, 0);
    load_tile(1, 1);

    float O[9][4];
#pragma unroll
    for (int i = 0; i < 9; i++)
#pragma unroll
        for (int j = 0; j < 4; j++) O[i][j] = 0.0f;
    float m0 = -3.0e38f, m1 = -3.0e38f, l0 = 0.0f, l1 = 0.0f;

    const int srcLo = (lane & ~3) | (tg >> 1);
    const int srcHi = srcLo | 2;
    const bool odd = lane & 1;
    const int m0r = warp * 16 + g;

    for (int t = 0; t < 32; t++) {
        if (t + 1 < 32)
            asm volatile("cp.async.wait_group 1;" ::: "memory");
        else
            asm volatile("cp.async.wait_group 0;" ::: "memory");
        __syncthreads();

        const uint32_t* bK = sK + (t & 1) * 2432;
        const uint32_t* bV = sVt + (t & 1) * 2880;

        float Sc[4][4];
#pragma unroll
        for (int i = 0; i < 4; i++)
#pragma unroll
            for (int j = 0; j < 4; j++) Sc[i][j] = 0.0f;
#pragma unroll
        for (int ks = 0; ks < 9; ks++) {
            const int kk = ks * 8 + tg;
            const uint32_t a0 = sQ[m0r * 76 + kk];
            const uint32_t a1 = sQ[(m0r + 8) * 76 + kk];
            const uint32_t a2 = sQ[m0r * 76 + kk + 4];
            const uint32_t a3 = sQ[(m0r + 8) * 76 + kk + 4];
#pragma unroll
            for (int na = 0; na < 4; na++) {
                const uint32_t b0 = bK[(na * 8 + g) * 76 + kk];
                const uint32_t b1 = bK[(na * 8 + g) * 76 + kk + 4];
                mma_tf32(Sc[na], a0, a1, a2, a3, b0, b1);
            }
        }

        float mx0 = -3.0e38f, mx1 = -3.0e38f;
#pragma unroll
        for (int na = 0; na < 4; na++) {
            mx0 = fmaxf(mx0, fmaxf(Sc[na][0], Sc[na][1]));
            mx1 = fmaxf(mx1, fmaxf(Sc[na][2], Sc[na][3]));
        }
        mx0 = fmaxf(mx0, __shfl_xor_sync(0xffffffffu, mx0, 1));
        mx0 = fmaxf(mx0, __shfl_xor_sync(0xffffffffu, mx0, 2));
        mx1 = fmaxf(mx1, __shfl_xor_sync(0xffffffffu, mx1, 1));
        mx1 = fmaxf(mx1, __shfl_xor_sync(0xffffffffu, mx1, 2));

        const float nm0 = fmaxf(m0, mx0), nm1 = fmaxf(m1, mx1);
        const float al0 = ex2f(m0 - nm0), al1 = ex2f(m1 - nm1);
        float s0 = 0.0f, s1 = 0.0f;
#pragma unroll
        for (int na = 0; na < 4; na++) {
            Sc[na][0] = ex2f(Sc[na][0] - nm0);
            Sc[na][1] = ex2f(Sc[na][1] - nm0);
            Sc[na][2] = ex2f(Sc[na][2] - nm1);
            Sc[na][3] = ex2f(Sc[na][3] - nm1);
            s0 += Sc[na][0] + Sc[na][1];
            s1 += Sc[na][2] + Sc[na][3];
        }
        s0 += __shfl_xor_sync(0xffffffffu, s0, 1);
        s0 += __shfl_xor_sync(0xffffffffu, s0, 2);
        s1 += __shfl_xor_sync(0xffffffffu, s1, 1);
        s1 += __shfl_xor_sync(0xffffffffu, s1, 2);
        l0 = l0 * al0 + s0;
        l1 = l1 * al1 + s1;
        m0 = nm0; m1 = nm1;
#pragma unroll
        for (int na = 0; na < 9; na++) {
            O[na][0] *= al0; O[na][1] *= al0;
            O[na][2] *= al1; O[na][3] *= al1;
        }

#pragma unroll
        for (int ks = 0; ks < 4; ks++) {
            const float y00 = __shfl_sync(0xffffffffu, Sc[ks][0], srcLo);
            const float y01 = __shfl_sync(0xffffffffu, Sc[ks][1], srcLo);
            const float y02 = __shfl_sync(0xffffffffu, Sc[ks][0], srcHi);
            const float y03 = __shfl_sync(0xffffffffu, Sc[ks][1], srcHi);
            const float y10 = __shfl_sync(0xffffffffu, Sc[ks][2], srcLo);
            const float y11 = __shfl_sync(0xffffffffu, Sc[ks][3], srcLo);
            const float y12 = __shfl_sync(0xffffffffu, Sc[ks][2], srcHi);
            const float y13 = __shfl_sync(0xffffffffu, Sc[ks][3], srcHi);
            const uint32_t a0 = f2tf(odd ? y01 : y00);
            const uint32_t a2 = f2tf(odd ? y03 : y02);
            const uint32_t a1 = f2tf(odd ? y11 : y10);
            const uint32_t a3 = f2tf(odd ? y13 : y12);
            const int kk = ks * 8 + tg;
#pragma unroll
            for (int na = 0; na < 9; na++) {
                const uint32_t b0 = bV[(na * 8 + g) * 40 + kk];
                const uint32_t b1 = bV[(na * 8 + g) * 40 + kk + 4];
                mma_tf32(O[na], a0, a1, a2, a3, b0, b1);
            }
        }

        __syncthreads();
        if (t + 2 < 32) load_tile(t + 2, t & 1);
    }

    const float i0 = 1.0f / l0, i1 = 1.0f / l1;
    const int r0 = qt * 64 + warp * 16 + g;
    uint32_t* out0 = P_AW + (size_t)(b * S_ + r0) * E_ + h * D_;
    uint32_t* out1 = P_AW + (size_t)(b * S_ + r0 + 8) * E_ + h * D_;
#pragma unroll
    for (int na = 0; na < 9; na++) {
        const int c = na * 8 + 2 * tg;
        *(uint2*)&out0[c] = make_uint2(f2tf(O[na][0] * i0), f2tf(O[na][1] * i0));
        *(uint2*)&out1[c] = make_uint2(f2tf(O[na][2] * i1), f2tf(O[na][3] * i1));
    }
}

// ---------------------------------------------------------------------------
// Output projection: fully cp.async (A=Atf tf32, B=owtf tf32), zero cvt.
// grid (1152/128, 8192/128), 256 threads.
// ---------------------------------------------------------------------------
__global__ void __launch_bounds__(256) out_gemm(const float* __restrict__ bias,
                                                float* __restrict__ outp)
{
    const int rowBase = blockIdx.y * 128;
    const int colBase = blockIdx.x * 128;
    const uint32_t* At = P_AW;   // [row][k] tf32
    const uint32_t* Wt = P_OWT;  // [k][n] tf32

    __shared__ __align__(16) uint32_t sA[2][128 * 20];
    __shared__ __align__(16) uint32_t sB[2][16 * 136];

    const int tid  = threadIdx.x;
    const int lane = tid & 31, warp = tid >> 5;
    const int wm = warp >> 2, wn = warp & 3;
    const int g = lane >> 2, tg = lane & 3;

    const int rowA = tid >> 1;
    const int kcA  = (tid & 1) * 8;
    const int krB  = tid >> 5;
    const int ncB  = (tid & 31) * 4;

    const uint32_t sA0 = smem_u32(&sA[0][0]);
    const uint32_t sA1 = smem_u32(&sA[1][0]);
    const uint32_t sB0 = smem_u32(&sB[0][0]);
    const uint32_t sB1 = smem_u32(&sB[1][0]);

    float acc[4][4][4];
#pragma unroll
    for (int i = 0; i < 4; i++)
#pragma unroll
        for (int j = 0; j < 4; j++)
#pragma unroll
            for (int l = 0; l < 4; l++) acc[i][j][l] = 0.0f;

    // prologue tile 0
    cpa16(sA0 + (rowA * 20 + kcA) * 4, At + (size_t)(rowBase + rowA) * E_ + kcA);
    cpa16(sA0 + (rowA * 20 + kcA + 4) * 4,
          At + (size_t)(rowBase + rowA) * E_ + kcA + 4);
    cpa16(sB0 + (krB * 136 + ncB) * 4, Wt + (size_t)krB * E_ + colBase + ncB);
    cpa16(sB0 + ((krB + 8) * 136 + ncB) * 4,
          Wt + (size_t)(krB + 8) * E_ + colBase + ncB);
    asm volatile("cp.async.commit_group;" ::: "memory");

    for (int t = 0; t < TQK; t++) {
        const int kt = t * 16;
        asm volatile("cp.async.wait_group 0;" ::: "memory");
        __syncthreads();
        if (t + 1 < TQK) {
            const uint32_t dA = ((t + 1) & 1) ? sA1 : sA0;
            const uint32_t dB = ((t + 1) & 1) ? sB1 : sB0;
            cpa16(dA + (rowA * 20 + kcA) * 4,
                  At + (size_t)(rowBase + rowA) * E_ + kt + 16 + kcA);
            cpa16(dA + (rowA * 20 + kcA + 4) * 4,
                  At + (size_t)(rowBase + rowA) * E_ + kt + 16 + kcA + 4);
            cpa16(dB + (krB * 136 + ncB) * 4,
                  Wt + (size_t)(kt + 16 + krB) * E_ + colBase + ncB);
            cpa16(dB + ((krB + 8) * 136 + ncB) * 4,
                  Wt + (size_t)(kt + 16 + krB + 8) * E_ + colBase + ncB);
            asm volatile("cp.async.commit_group;" ::: "memory");
        }

        const uint32_t* As = sA[t & 1];
        const uint32_t* Bv = sB[t & 1];
#pragma unroll
        for (int ks = 0; ks < 2; ks++) {
            const int kk = ks * 8 + tg;
            uint32_t af[4][4], bf[4][2];
#pragma unroll
            for (int ma = 0; ma < 4; ma++) {
                const int m0 = wm * 64 + ma * 16 + g;
                af[ma][0] = As[m0 * 20 + kk];
                af[ma][1] = As[(m0 + 8) * 20 + kk];
                af[ma][2] = As[m0 * 20 + kk + 4];
                af[ma][3] = As[(m0 + 8) * 20 + kk + 4];
            }
#pragma unroll
            for (int na = 0; na < 4; na++) {
                const int n0 = wn * 32 + na * 8 + g;
                bf[na][0] = Bv[kk * 136 + n0];
                bf[na][1] = Bv[(kk + 4) * 136 + n0];
            }
#pragma unroll
            for (int ma = 0; ma < 4; ma++)
#pragma unroll
                for (int na = 0; na < 4; na++)
                    mma_tf32(acc[ma][na], af[ma][0], af[ma][1], af[ma][2],
                             af[ma][3], bf[na][0], bf[na][1]);
        }
    }

#pragma unroll
    for (int ma = 0; ma < 4; ma++) {
#pragma unroll
        for (int na = 0; na < 4; na++) {
            const int c = colBase + wn * 32 + na * 8 + 2 * tg;
            const float bx = bias[c];
            const float by = bias[c + 1];
#pragma unroll
            for (int half = 0; half < 2; half++) {
                const int r = rowBase + wm * 64 + ma * 16 + g + half * 8;
                float2 ov;
                ov.x = acc[ma][na][half * 2 + 0] + bx;
                ov.y = acc[ma][na][half * 2 + 1] + by;
                *(float2*)&outp[(size_t)r * E_ + c] = ov;
            }
        }
    }
}

// ---------------------------------------------------------------------------
extern "C" void kernel_launch(void* const* d_in, const int* in_sizes, int n_in,
                              void* d_out, int out_size)
{
    const float* q    = (const float*)d_in[0];
    const float* k    = (const float*)d_in[1];
    const float* v    = (const float*)d_in[2];
    const float* W    = (const float*)d_in[3];
    const float* bias = (const float*)d_in[4];
    const float* ow   = (const float*)d_in[5];
    const float* ob   = (const float*)d_in[6];
    float* out = (float*)d_out;

    cudaFuncSetAttribute(attn_kernel,
                         cudaFuncAttributeMaxDynamicSharedMemorySize, 61952);

    // in_proj W -> tf32 at P_AW (region later becomes Atf)
    cvt_arr<<<1024, 256>>>((const float4*)W, 3ull * CH_, E_ * W3E / 4);

    qkv_gemm<<<dim3(E_ / 128, NROW / 128, 3), 256>>>(q, k, v, bias);

    attn_kernel<<<dim3(S_ / 64, H_, B_), 128, 61952>>>();

    // out_w -> tf32 at P_OWT (overwrites dead Qs region)
    cvt_arr<<<512, 256>>>((const float4*)ow, 0, E_ * E_ / 4);

    out_gemm<<<dim3(E_ / 128, NROW / 128, 1), 256>>>(ob, out);
}

// round 13
// speedup vs baseline: 7.5929x; 1.6644x over previous
#include <cuda_runtime.h>
#include <cuda_fp16.h>
#include <cstdint>

#define B_   8
#define S_   1024
#define E_   1152
#define H_   16
#define D_   72
#define NROW (B_ * S_)
#define W3E  (3 * E_)
#define CH_  (B_ * H_ * S_ * D_)   // 9437184
#define EW   (E_ / 2)              // 576 h2-words per embed row
#define DW   (D_ / 2)              // 36 h2-words per head row

// ------- device scratch: EXACT proven shape (single 144 MiB pool) -------
// word-offset map (all regions fit in 4*CH_ words):
//   [0,          CH_/2)   Qh   (fp16x2, pre-scaled)      4,718,592 w
//   [CH_/2,      CH_)     Kh   (fp16x2)                  4,718,592 w
//   [CH_,        3CH_/2)  Vh   (fp16 halves, [b,h,d,s])  4,718,592 w
//   [3CH_/2,     2CH_)    Ah   (fp16x2 attn out)         4,718,592 w
//   [2CH_, +1990656)      Wh2  (in_proj packed)          1,990,656 w
//   [.., +663552)         owh2 (out_w packed)              663,552 w
__device__ uint32_t g_pool[4ull * CH_];

#define OFF_W   (2ull * CH_)
#define OFF_OW  (2ull * CH_ + 1990656ull)
#define P_Q     (g_pool)
#define P_KH    (g_pool + (size_t)CH_ / 2)
#define P_VH    ((uint16_t*)(g_pool + (size_t)CH_))
#define P_AH    (g_pool + 3ull * CH_ / 2)
#define P_WH    (g_pool + OFF_W)
#define P_OWH   (g_pool + OFF_OW)

// ---------------- helpers ----------------
__device__ __forceinline__ uint32_t h2pack(float lo, float hi) {
    uint32_t r;
    asm("cvt.rn.f16x2.f32 %0, %1, %2;" : "=r"(r) : "f"(hi), "f"(lo));
    return r;
}
__device__ __forceinline__ float ex2f(float x) {
    float y;
    asm("ex2.approx.f32 %0, %1;" : "=f"(y) : "f"(x));
    return y;
}
__device__ __forceinline__ uint32_t smem_u32(const void* p) {
    uint32_t a;
    asm("{ .reg .u64 t; cvta.to.shared.u64 t, %1; cvt.u32.u64 %0, t; }"
        : "=r"(a) : "l"(p));
    return a;
}
__device__ __forceinline__ void cpa16(uint32_t s, const void* g) {
    asm volatile("cp.async.cg.shared.global [%0], [%1], 16;"
                 :: "r"(s), "l"(g) : "memory");
}
__device__ __forceinline__ void mma_f16(float (&c)[4],
    uint32_t a0, uint32_t a1, uint32_t a2, uint32_t a3,
    uint32_t b0, uint32_t b1)
{
    asm volatile(
        "mma.sync.aligned.m16n8k16.row.col.f32.f16.f16.f32 "
        "{%0,%1,%2,%3}, {%4,%5,%6,%7}, {%8,%9}, {%0,%1,%2,%3};\n"
        : "+f"(c[0]), "+f"(c[1]), "+f"(c[2]), "+f"(c[3])
        : "r"(a0), "r"(a1), "r"(a2), "r"(a3), "r"(b0), "r"(b1));
}

// ---------------------------------------------------------------------------
// Weight pack: fp32 [K][N] -> h2 words [kw][N] at pool word offset.
// word = (W[2kw][n], W[2kw+1][n])
// ---------------------------------------------------------------------------
__global__ void packW(const float* __restrict__ src, size_t dst_off,
                      int ncols, int n4c, int total4) {
    const int i = blockIdx.x * blockDim.x + threadIdx.x;
    if (i >= total4) return;
    uint32_t* dst = g_pool + dst_off;
    const int kw = i / n4c, n = (i - kw * n4c) * 4;
    const float4 lo = *(const float4*)&src[(size_t)(2 * kw) * ncols + n];
    const float4 hi = *(const float4*)&src[(size_t)(2 * kw + 1) * ncols + n];
    uint4 o;
    o.x = h2pack(lo.x, hi.x);
    o.y = h2pack(lo.y, hi.y);
    o.z = h2pack(lo.z, hi.z);
    o.w = h2pack(lo.w, hi.w);
    ((uint4*)dst)[i] = o;
}

// ---------------------------------------------------------------------------
// QKV GEMM (fp16 mma): A fp32 reg-staged (pack at STS), B h2 via 3-stage cp.async.
// Tile = 16 k-halves (8 words), 72 tiles. Epilogue -> Qh (scaled), Kh, Vh (transp).
// grid (9, 64, 3), 256 threads (8 warps as 2m x 4n, warp tile 64x32).
// ---------------------------------------------------------------------------
#define TQ 72

__global__ void __launch_bounds__(256) qkv_gemm(
    const float* __restrict__ q, const float* __restrict__ k,
    const float* __restrict__ v, const float* __restrict__ bias)
{
    const int z = blockIdx.z;
    const float* X = (z == 0) ? q : (z == 1) ? k : v;
    const uint32_t* Wt = P_WH;

    const int rowBase = blockIdx.y * 128;
    const int colBase = blockIdx.x * 128;
    const int wcol0   = z * E_ + colBase;

    __shared__ __align__(16) uint32_t sA[2][128 * 12];
    __shared__ __align__(16) uint32_t sB[3][8 * 136];

    const int tid  = threadIdx.x;
    const int lane = tid & 31, warp = tid >> 5;
    const int wm = warp >> 2, wn = warp & 3;
    const int g = lane >> 2, tg = lane & 3;

    const int rowA = tid >> 1;          // 0..127
    const int kcA  = (tid & 1) * 4;     // word col 0 or 4
    const int krB  = tid >> 5;          // 0..7
    const int ncB  = (tid & 31) * 4;

    const uint32_t sBb = smem_u32(&sB[0][0]);

    float acc[4][4][4];
#pragma unroll
    for (int i = 0; i < 4; i++)
#pragma unroll
        for (int j = 0; j < 4; j++)
#pragma unroll
            for (int l = 0; l < 4; l++) acc[i][j][l] = 0.0f;

    float4 a0v, a1v;

    auto loadB = [&](int t) {
        const uint32_t dB = sBb + (uint32_t)(t % 3) * (8 * 136 * 4);
        cpa16(dB + (krB * 136 + ncB) * 4,
              Wt + (size_t)(t * 8 + krB) * W3E + wcol0 + ncB);
        asm volatile("cp.async.commit_group;" ::: "memory");
    };

    // ---- prologue ----
    a0v = *(const float4*)&X[(size_t)(rowBase + rowA) * E_ + (tid & 1) * 8];
    a1v = *(const float4*)&X[(size_t)(rowBase + rowA) * E_ + (tid & 1) * 8 + 4];
    *(uint4*)&sA[0][rowA * 12 + kcA] =
        make_uint4(h2pack(a0v.x, a0v.y), h2pack(a0v.z, a0v.w),
                   h2pack(a1v.x, a1v.y), h2pack(a1v.z, a1v.w));
    loadB(0);
    loadB(1);

    for (int t = 0; t < TQ; t++) {
        if (t + 1 < TQ) {
            const size_t fb = (size_t)(rowBase + rowA) * E_ + (t + 1) * 16 + (tid & 1) * 8;
            a0v = *(const float4*)&X[fb];
            a1v = *(const float4*)&X[fb + 4];
        }
        if (t + 1 < TQ)
            asm volatile("cp.async.wait_group 1;" ::: "memory");
        else
            asm volatile("cp.async.wait_group 0;" ::: "memory");
        __syncthreads();
        if (t + 2 < TQ) loadB(t + 2);

        const uint32_t* As = sA[t & 1];
        const uint32_t* Bv = sB[t % 3];
        uint32_t af[4][4], bf[4][2];
#pragma unroll
        for (int ma = 0; ma < 4; ma++) {
            const int m0 = wm * 64 + ma * 16 + g;
            af[ma][0] = As[m0 * 12 + tg];
            af[ma][1] = As[(m0 + 8) * 12 + tg];
            af[ma][2] = As[m0 * 12 + tg + 4];
            af[ma][3] = As[(m0 + 8) * 12 + tg + 4];
        }
#pragma unroll
        for (int na = 0; na < 4; na++) {
            const int n0 = wn * 32 + na * 8 + g;
            bf[na][0] = Bv[tg * 136 + n0];
            bf[na][1] = Bv[(tg + 4) * 136 + n0];
        }
#pragma unroll
        for (int ma = 0; ma < 4; ma++)
#pragma unroll
            for (int na = 0; na < 4; na++)
                mma_f16(acc[ma][na], af[ma][0], af[ma][1], af[ma][2],
                        af[ma][3], bf[na][0], bf[na][1]);

        if (t + 1 < TQ) {
            uint32_t* A2 = sA[(t + 1) & 1];
            *(uint4*)&A2[rowA * 12 + kcA] =
                make_uint4(h2pack(a0v.x, a0v.y), h2pack(a0v.z, a0v.w),
                           h2pack(a1v.x, a1v.y), h2pack(a1v.z, a1v.w));
        }
    }

    // ---- epilogue: attention-ready fp16 operands (Q folds 72^-0.5 * log2 e) ----
    const float scale = 0.17002325737443355f;
#pragma unroll
    for (int ma = 0; ma < 4; ma++) {
#pragma unroll
        for (int na = 0; na < 4; na++) {
            const int c  = colBase + wn * 32 + na * 8 + 2 * tg;   // even
            const float bx = bias[z * E_ + c];
            const float by = bias[z * E_ + c + 1];
            const int hh = c / D_;
            const int dd = c - hh * D_;
#pragma unroll
            for (int half = 0; half < 2; half++) {
                const int r = rowBase + wm * 64 + ma * 16 + g + half * 8;
                const int bb = r >> 10, ss = r & 1023;
                const float vx = acc[ma][na][half * 2 + 0] + bx;
                const float vy = acc[ma][na][half * 2 + 1] + by;
                if (z == 0) {
                    P_Q[((size_t)(bb * H_ + hh) * S_ + ss) * DW + (dd >> 1)] =
                        h2pack(vx * scale, vy * scale);
                } else if (z == 1) {
                    P_KH[((size_t)(bb * H_ + hh) * S_ + ss) * DW + (dd >> 1)] =
                        h2pack(vx, vy);
                } else {
                    const size_t vi = ((size_t)(bb * H_ + hh) * D_ + dd) * S_ + ss;
                    P_VH[vi]      = __half_as_ushort(__float2half_rn(vx));
                    P_VH[vi + S_] = __half_as_ushort(__float2half_rn(vy));
                }
            }
        }
    }
}

// ---------------------------------------------------------------------------
// Flash attention (fp16 mma, exp2 softmax, cp.async double-buffered K/V).
// smem: sQ[64][44] | sK[2][32][44] | sVt[2][72][20] ~ 34 KB static.
// K-dim padded 72->80 halves (pad words zeroed). grid (S/64, H, B), 128 thr.
// ---------------------------------------------------------------------------
__global__ void __launch_bounds__(128) attn_kernel()
{
    __shared__ __align__(16) uint32_t sQ[64 * 44];
    __shared__ __align__(16) uint32_t sK[2 * 32 * 44];
    __shared__ __align__(16) uint32_t sVt[2 * 72 * 20];

    const int qt = blockIdx.x, h = blockIdx.y, b = blockIdx.z;
    const int tid = threadIdx.x;
    const int lane = tid & 31, warp = tid >> 5;
    const int g = lane >> 2, tg = lane & 3;

    const uint32_t sQb = smem_u32(sQ);
    const uint32_t sKb = smem_u32(sK);
    const uint32_t sVb = smem_u32(sVt);

    const uint32_t* Qg = P_Q  + ((size_t)(b * H_ + h) * S_ + qt * 64) * DW;
    const uint32_t* Kg = P_KH + (size_t)(b * H_ + h) * S_ * DW;
    const uint16_t* Vg = P_VH + (size_t)(b * H_ + h) * D_ * S_;

    // zero k-pad words (36..39) of sQ and both sK buffers
    for (int i = tid; i < 512; i += 128) {
        const int r = (i & 255) >> 2, w = 36 + (i & 3);
        if (i < 256) sQ[r * 44 + w] = 0;
        else         sK[r * 44 + w] = 0;
    }

    auto load_tile = [&](int t, int buf) {
        const int kt = t * 32;
        const uint32_t dK = sKb + (uint32_t)buf * (32 * 44 * 4);
        const uint32_t dV = sVb + (uint32_t)buf * (72 * 20 * 4);
#pragma unroll
        for (int j = 0; j < 3; j++) {              // K: 32 rows x 9 chunks = 288
            const int idx = j * 128 + tid;
            if (idx < 288) {
                const int r = idx / 9, c = (idx % 9) * 4;
                cpa16(dK + (r * 44 + c) * 4, Kg + (size_t)(kt + r) * DW + c);
            }
        }
#pragma unroll
        for (int j = 0; j < 3; j++) {              // V: 72 rows x 4 chunks = 288
            const int idx = j * 128 + tid;
            if (idx < 288) {
                const int d = idx >> 2, c = idx & 3;
                cpa16(dV + (d * 20 + c * 4) * 4, Vg + (size_t)d * S_ + kt + c * 8);
            }
        }
        asm volatile("cp.async.commit_group;" ::: "memory");
    };

    // prologue: Q (64 rows x 9 chunks = 576, folded into group 0) + tiles 0,1
#pragma unroll
    for (int j = 0; j < 5; j++) {
        const int idx = j * 128 + tid;
        if (idx < 576) {
            const int r = idx / 9, c = (idx % 9) * 4;
            cpa16(sQb + (r * 44 + c) * 4, Qg + (size_t)r * DW + c);
        }
    }
    load_tile(0, 0);
    load_tile(1, 1);

    float O[9][4];
#pragma unroll
    for (int i = 0; i < 9; i++)
#pragma unroll
        for (int j = 0; j < 4; j++) O[i][j] = 0.0f;
    float m0 = -3.0e38f, m1 = -3.0e38f, l0 = 0.0f, l1 = 0.0f;
    const int m0r = warp * 16 + g;

    for (int t = 0; t < 32; t++) {
        if (t + 1 < 32)
            asm volatile("cp.async.wait_group 1;" ::: "memory");
        else
            asm volatile("cp.async.wait_group 0;" ::: "memory");
        __syncthreads();

        const uint32_t* bK = sK + (t & 1) * (32 * 44);
        const uint32_t* bV = sVt + (t & 1) * (72 * 20);

        // S = Q K^T (k = 80 halves = 5 k16 steps; pad zeroed)
        float Sc[4][4];
#pragma unroll
        for (int i = 0; i < 4; i++)
#pragma unroll
            for (int j = 0; j < 4; j++) Sc[i][j] = 0.0f;
#pragma unroll
        for (int ks = 0; ks < 5; ks++) {
            const int kk = ks * 8 + tg;
            const uint32_t a0 = sQ[m0r * 44 + kk];
            const uint32_t a1 = sQ[(m0r + 8) * 44 + kk];
            const uint32_t a2 = sQ[m0r * 44 + kk + 4];
            const uint32_t a3 = sQ[(m0r + 8) * 44 + kk + 4];
#pragma unroll
            for (int na = 0; na < 4; na++) {
                const uint32_t b0 = bK[(na * 8 + g) * 44 + kk];
                const uint32_t b1 = bK[(na * 8 + g) * 44 + kk + 4];
                mma_f16(Sc[na], a0, a1, a2, a3, b0, b1);
            }
        }

        // online softmax (exp2 domain)
        float mx0 = -3.0e38f, mx1 = -3.0e38f;
#pragma unroll
        for (int na = 0; na < 4; na++) {
            mx0 = fmaxf(mx0, fmaxf(Sc[na][0], Sc[na][1]));
            mx1 = fmaxf(mx1, fmaxf(Sc[na][2], Sc[na][3]));
        }
        mx0 = fmaxf(mx0, __shfl_xor_sync(0xffffffffu, mx0, 1));
        mx0 = fmaxf(mx0, __shfl_xor_sync(0xffffffffu, mx0, 2));
        mx1 = fmaxf(mx1, __shfl_xor_sync(0xffffffffu, mx1, 1));
        mx1 = fmaxf(mx1, __shfl_xor_sync(0xffffffffu, mx1, 2));

        const float nm0 = fmaxf(m0, mx0), nm1 = fmaxf(m1, mx1);
        const float al0 = ex2f(m0 - nm0), al1 = ex2f(m1 - nm1);
        float s0 = 0.0f, s1 = 0.0f;
#pragma unroll
        for (int na = 0; na < 4; na++) {
            Sc[na][0] = ex2f(Sc[na][0] - nm0);
            Sc[na][1] = ex2f(Sc[na][1] - nm0);
            Sc[na][2] = ex2f(Sc[na][2] - nm1);
            Sc[na][3] = ex2f(Sc[na][3] - nm1);
            s0 += Sc[na][0] + Sc[na][1];
            s1 += Sc[na][2] + Sc[na][3];
        }
        s0 += __shfl_xor_sync(0xffffffffu, s0, 1);
        s0 += __shfl_xor_sync(0xffffffffu, s0, 2);
        s1 += __shfl_xor_sync(0xffffffffu, s1, 1);
        s1 += __shfl_xor_sync(0xffffffffu, s1, 2);
        l0 = l0 * al0 + s0;
        l1 = l1 * al1 + s1;
        m0 = nm0; m1 = nm1;
#pragma unroll
        for (int na = 0; na < 9; na++) {
            O[na][0] *= al0; O[na][1] *= al0;
            O[na][2] *= al1; O[na][3] *= al1;
        }

        // O += P V : fp16 A-frags straight from S accumulators (no shuffles)
#pragma unroll
        for (int ks = 0; ks < 2; ks++) {
            const uint32_t a0 = h2pack(Sc[2 * ks][0],     Sc[2 * ks][1]);
            const uint32_t a1 = h2pack(Sc[2 * ks][2],     Sc[2 * ks][3]);
            const uint32_t a2 = h2pack(Sc[2 * ks + 1][0], Sc[2 * ks + 1][1]);
            const uint32_t a3 = h2pack(Sc[2 * ks + 1][2], Sc[2 * ks + 1][3]);
            const int kk = ks * 8 + tg;
#pragma unroll
            for (int na = 0; na < 9; na++) {
                const uint32_t b0 = bV[(na * 8 + g) * 20 + kk];
                const uint32_t b1 = bV[(na * 8 + g) * 20 + kk + 4];
                mma_f16(O[na], a0, a1, a2, a3, b0, b1);
            }
        }

        __syncthreads();
        if (t + 2 < 32) load_tile(t + 2, t & 1);
    }

    // epilogue -> Ah (fp16)
    const float i0 = 1.0f / l0, i1 = 1.0f / l1;
    const int r0 = qt * 64 + warp * 16 + g;
    uint32_t* out0 = P_AH + (size_t)(b * S_ + r0) * EW + h * DW;
    uint32_t* out1 = P_AH + (size_t)(b * S_ + r0 + 8) * EW + h * DW;
#pragma unroll
    for (int na = 0; na < 9; na++) {
        const int cw = na * 4 + tg;
        out0[cw] = h2pack(O[na][0] * i0, O[na][1] * i0);
        out1[cw] = h2pack(O[na][2] * i1, O[na][3] * i1);
    }
}

// ---------------------------------------------------------------------------
// Output projection (fp16 mma): A=Ah, B=owh2, both via 2-stage cp.async.
// grid (9, 64), 256 threads.
// ---------------------------------------------------------------------------
__global__ void __launch_bounds__(256) out_gemm(const float* __restrict__ bias,
                                                float* __restrict__ outp)
{
    const int rowBase = blockIdx.y * 128;
    const int colBase = blockIdx.x * 128;
    const uint32_t* At = P_AH;
    const uint32_t* Wt = P_OWH;

    __shared__ __align__(16) uint32_t sA[2][128 * 12];
    __shared__ __align__(16) uint32_t sB[2][8 * 136];

    const int tid  = threadIdx.x;
    const int lane = tid & 31, warp = tid >> 5;
    const int wm = warp >> 2, wn = warp & 3;
    const int g = lane >> 2, tg = lane & 3;

    const int rowA = tid >> 1;
    const int kcA  = (tid & 1) * 4;
    const int krB  = tid >> 5;
    const int ncB  = (tid & 31) * 4;

    const uint32_t sA0 = smem_u32(&sA[0][0]);
    const uint32_t sA1 = smem_u32(&sA[1][0]);
    const uint32_t sB0 = smem_u32(&sB[0][0]);
    const uint32_t sB1 = smem_u32(&sB[1][0]);

    float acc[4][4][4];
#pragma unroll
    for (int i = 0; i < 4; i++)
#pragma unroll
        for (int j = 0; j < 4; j++)
#pragma unroll
            for (int l = 0; l < 4; l++) acc[i][j][l] = 0.0f;

    auto load_stage = [&](int t, uint32_t dA, uint32_t dB) {
        cpa16(dA + (rowA * 12 + kcA) * 4,
              At + (size_t)(rowBase + rowA) * EW + t * 8 + kcA);
        cpa16(dB + (krB * 136 + ncB) * 4,
              Wt + (size_t)(t * 8 + krB) * E_ + colBase + ncB);
        asm volatile("cp.async.commit_group;" ::: "memory");
    };

    load_stage(0, sA0, sB0);

    for (int t = 0; t < TQ; t++) {
        asm volatile("cp.async.wait_group 0;" ::: "memory");
        __syncthreads();
        if (t + 1 < TQ)
            load_stage(t + 1, ((t + 1) & 1) ? sA1 : sA0, ((t + 1) & 1) ? sB1 : sB0);

        const uint32_t* As = sA[t & 1];
        const uint32_t* Bv = sB[t & 1];
        uint32_t af[4][4], bf[4][2];
#pragma unroll
        for (int ma = 0; ma < 4; ma++) {
            const int m0 = wm * 64 + ma * 16 + g;
            af[ma][0] = As[m0 * 12 + tg];
            af[ma][1] = As[(m0 + 8) * 12 + tg];
            af[ma][2] = As[m0 * 12 + tg + 4];
            af[ma][3] = As[(m0 + 8) * 12 + tg + 4];
        }
#pragma unroll
        for (int na = 0; na < 4; na++) {
            const int n0 = wn * 32 + na * 8 + g;
            bf[na][0] = Bv[tg * 136 + n0];
            bf[na][1] = Bv[(tg + 4) * 136 + n0];
        }
#pragma unroll
        for (int ma = 0; ma < 4; ma++)
#pragma unroll
            for (int na = 0; na < 4; na++)
                mma_f16(acc[ma][na], af[ma][0], af[ma][1], af[ma][2],
                        af[ma][3], bf[na][0], bf[na][1]);
    }

#pragma unroll
    for (int ma = 0; ma < 4; ma++) {
#pragma unroll
        for (int na = 0; na < 4; na++) {
            const int c = colBase + wn * 32 + na * 8 + 2 * tg;
            const float bx = bias[c];
            const float by = bias[c + 1];
#pragma unroll
            for (int half = 0; half < 2; half++) {
                const int r = rowBase + wm * 64 + ma * 16 + g + half * 8;
                float2 ov;
                ov.x = acc[ma][na][half * 2 + 0] + bx;
                ov.y = acc[ma][na][half * 2 + 1] + by;
                *(float2*)&outp[(size_t)r * E_ + c] = ov;
            }
        }
    }
}

// ---------------------------------------------------------------------------
extern "C" void kernel_launch(void* const* d_in, const int* in_sizes, int n_in,
                              void* d_out, int out_size)
{
    const float* q    = (const float*)d_in[0];
    const float* k    = (const float*)d_in[1];
    const float* v    = (const float*)d_in[2];
    const float* W    = (const float*)d_in[3];
    const float* bias = (const float*)d_in[4];
    const float* ow   = (const float*)d_in[5];
    const float* ob   = (const float*)d_in[6];
    float* out = (float*)d_out;

    packW<<<(EW * (W3E / 4) + 255) / 256, 256>>>(W, OFF_W, W3E, W3E / 4,
                                                 EW * (W3E / 4));
    packW<<<(EW * (E_ / 4) + 255) / 256, 256>>>(ow, OFF_OW, E_, E_ / 4,
                                                EW * (E_ / 4));

    qkv_gemm<<<dim3(E_ / 128, NROW / 128, 3), 256>>>(q, k, v, bias);

    attn_kernel<<<dim3(S_ / 64, H_, B_), 128>>>();

    out_gemm<<<dim3(E_ / 128, NROW / 128), 256>>>(ob, out);
}

// round 14
// speedup vs baseline: 7.7166x; 1.0163x over previous
#include <cuda_runtime.h>
#include <cuda_fp16.h>
#include <cstdint>

#define B_   8
#define S_   1024
#define E_   1152
#define H_   16
#define D_   72
#define NROW (B_ * S_)
#define W3E  (3 * E_)
#define CH_  (B_ * H_ * S_ * D_)   // 9437184
#define EW   (E_ / 2)              // 576 h2-words per embed row
#define DW   (D_ / 2)              // 36 h2-words per head row

// ------- device scratch: EXACT proven shape (single 144 MiB pool) -------
__device__ uint32_t g_pool[4ull * CH_];

#define OFF_W   (2ull * CH_)
#define OFF_OW  (2ull * CH_ + 1990656ull)
#define P_Q     (g_pool)
#define P_KH    (g_pool + (size_t)CH_ / 2)
#define P_VH    ((uint16_t*)(g_pool + (size_t)CH_))
#define P_AH    (g_pool + 3ull * CH_ / 2)
#define P_WH    (g_pool + OFF_W)
#define P_OWH   (g_pool + OFF_OW)

// ---------------- helpers ----------------
__device__ __forceinline__ uint32_t h2pack(float lo, float hi) {
    uint32_t r;
    asm("cvt.rn.f16x2.f32 %0, %1, %2;" : "=r"(r) : "f"(hi), "f"(lo));
    return r;
}
__device__ __forceinline__ float ex2f(float x) {
    float y;
    asm("ex2.approx.f32 %0, %1;" : "=f"(y) : "f"(x));
    return y;
}
__device__ __forceinline__ uint32_t smem_u32(const void* p) {
    uint32_t a;
    asm("{ .reg .u64 t; cvta.to.shared.u64 t, %1; cvt.u32.u64 %0, t; }"
        : "=r"(a) : "l"(p));
    return a;
}
__device__ __forceinline__ void cpa16(uint32_t s, const void* g) {
    asm volatile("cp.async.cg.shared.global [%0], [%1], 16;"
                 :: "r"(s), "l"(g) : "memory");
}
__device__ __forceinline__ void mma_f16(float (&c)[4],
    uint32_t a0, uint32_t a1, uint32_t a2, uint32_t a3,
    uint32_t b0, uint32_t b1)
{
    asm volatile(
        "mma.sync.aligned.m16n8k16.row.col.f32.f16.f16.f32 "
        "{%0,%1,%2,%3}, {%4,%5,%6,%7}, {%8,%9}, {%0,%1,%2,%3};\n"
        : "+f"(c[0]), "+f"(c[1]), "+f"(c[2]), "+f"(c[3])
        : "r"(a0), "r"(a1), "r"(a2), "r"(a3), "r"(b0), "r"(b1));
}

// ---------------------------------------------------------------------------
// Weight pack: fp32 [K][N] -> h2 words [kw][N] at pool word offset.
// ---------------------------------------------------------------------------
__global__ void packW(const float* __restrict__ src, size_t dst_off,
                      int ncols, int n4c, int total4) {
    const int i = blockIdx.x * blockDim.x + threadIdx.x;
    if (i >= total4) return;
    uint32_t* dst = g_pool + dst_off;
    const int kw = i / n4c, n = (i - kw * n4c) * 4;
    const float4 lo = *(const float4*)&src[(size_t)(2 * kw) * ncols + n];
    const float4 hi = *(const float4*)&src[(size_t)(2 * kw + 1) * ncols + n];
    uint4 o;
    o.x = h2pack(lo.x, hi.x);
    o.y = h2pack(lo.y, hi.y);
    o.z = h2pack(lo.z, hi.z);
    o.w = h2pack(lo.w, hi.w);
    ((uint4*)dst)[i] = o;
}

// ---------------------------------------------------------------------------
// QKV GEMM (fp16 mma): k-tile = 32 halves (16 words), 36 iterations.
// A fp32 reg-staged (pack at STS.128), B h2 via 3-stage cp.async.
// grid (9, 64, 3), 256 threads (8 warps as 2m x 4n, warp tile 64x32).
// ---------------------------------------------------------------------------
#define TQ2 36

__global__ void __launch_bounds__(256) qkv_gemm(
    const float* __restrict__ q, const float* __restrict__ k,
    const float* __restrict__ v, const float* __restrict__ bias)
{
    const int z = blockIdx.z;
    const float* X = (z == 0) ? q : (z == 1) ? k : v;
    const uint32_t* Wt = P_WH;

    const int rowBase = blockIdx.y * 128;
    const int colBase = blockIdx.x * 128;
    const int wcol0   = z * E_ + colBase;

    __shared__ __align__(16) uint32_t sA[2][128 * 20];
    __shared__ __align__(16) uint32_t sB[3][16 * 136];

    const int tid  = threadIdx.x;
    const int lane = tid & 31, warp = tid >> 5;
    const int wm = warp >> 2, wn = warp & 3;
    const int g = lane >> 2, tg = lane & 3;

    const int rowA = tid >> 1;          // 0..127
    const int kcA  = (tid & 1) * 8;     // word col 0 or 8
    const int krB  = tid >> 5;          // 0..7 (and +8)
    const int ncB  = (tid & 31) * 4;

    const uint32_t sBb = smem_u32(&sB[0][0]);

    float acc[4][4][4];
#pragma unroll
    for (int i = 0; i < 4; i++)
#pragma unroll
        for (int j = 0; j < 4; j++)
#pragma unroll
            for (int l = 0; l < 4; l++) acc[i][j][l] = 0.0f;

    float4 a0v, a1v, a2v, a3v;   // 16 floats -> 8 h2 words per thread per tile

    auto loadA_g = [&](int t) {
        const size_t fb = (size_t)(rowBase + rowA) * E_ + t * 32 + (tid & 1) * 16;
        a0v = *(const float4*)&X[fb];
        a1v = *(const float4*)&X[fb + 4];
        a2v = *(const float4*)&X[fb + 8];
        a3v = *(const float4*)&X[fb + 12];
    };
    auto storeA_s = [&](int buf) {
        uint32_t* A = sA[buf];
        *(uint4*)&A[rowA * 20 + kcA] =
            make_uint4(h2pack(a0v.x, a0v.y), h2pack(a0v.z, a0v.w),
                       h2pack(a1v.x, a1v.y), h2pack(a1v.z, a1v.w));
        *(uint4*)&A[rowA * 20 + kcA + 4] =
            make_uint4(h2pack(a2v.x, a2v.y), h2pack(a2v.z, a2v.w),
                       h2pack(a3v.x, a3v.y), h2pack(a3v.z, a3v.w));
    };
    auto loadB = [&](int t) {
        const uint32_t dB = sBb + (uint32_t)(t % 3) * (16 * 136 * 4);
        cpa16(dB + (krB * 136 + ncB) * 4,
              Wt + (size_t)(t * 16 + krB) * W3E + wcol0 + ncB);
        cpa16(dB + ((krB + 8) * 136 + ncB) * 4,
              Wt + (size_t)(t * 16 + krB + 8) * W3E + wcol0 + ncB);
        asm volatile("cp.async.commit_group;" ::: "memory");
    };

    // ---- prologue ----
    loadA_g(0);
    storeA_s(0);
    loadB(0);
    loadB(1);

    for (int t = 0; t < TQ2; t++) {
        if (t + 1 < TQ2) loadA_g(t + 1);
        if (t + 1 < TQ2)
            asm volatile("cp.async.wait_group 1;" ::: "memory");
        else
            asm volatile("cp.async.wait_group 0;" ::: "memory");
        __syncthreads();
        if (t + 2 < TQ2) loadB(t + 2);

        const uint32_t* As = sA[t & 1];
        const uint32_t* Bv = sB[t % 3];
#pragma unroll
        for (int ks = 0; ks < 2; ks++) {
            const int kk = ks * 8 + tg;
            uint32_t af[4][4], bf[4][2];
#pragma unroll
            for (int ma = 0; ma < 4; ma++) {
                const int m0 = wm * 64 + ma * 16 + g;
                af[ma][0] = As[m0 * 20 + kk];
                af[ma][1] = As[(m0 + 8) * 20 + kk];
                af[ma][2] = As[m0 * 20 + kk + 4];
                af[ma][3] = As[(m0 + 8) * 20 + kk + 4];
            }
#pragma unroll
            for (int na = 0; na < 4; na++) {
                const int n0 = wn * 32 + na * 8 + g;
                bf[na][0] = Bv[kk * 136 + n0];
                bf[na][1] = Bv[(kk + 4) * 136 + n0];
            }
#pragma unroll
            for (int ma = 0; ma < 4; ma++)
#pragma unroll
                for (int na = 0; na < 4; na++)
                    mma_f16(acc[ma][na], af[ma][0], af[ma][1], af[ma][2],
                            af[ma][3], bf[na][0], bf[na][1]);
        }

        if (t + 1 < TQ2) storeA_s((t + 1) & 1);
    }

    // ---- epilogue: attention-ready fp16 operands (Q folds 72^-0.5 * log2 e) ----
    const float scale = 0.17002325737443355f;
#pragma unroll
    for (int ma = 0; ma < 4; ma++) {
#pragma unroll
        for (int na = 0; na < 4; na++) {
            const int c  = colBase + wn * 32 + na * 8 + 2 * tg;   // even
            const float bx = bias[z * E_ + c];
            const float by = bias[z * E_ + c + 1];
            const int hh = c / D_;
            const int dd = c - hh * D_;
#pragma unroll
            for (int half = 0; half < 2; half++) {
                const int r = rowBase + wm * 64 + ma * 16 + g + half * 8;
                const int bb = r >> 10, ss = r & 1023;
                const float vx = acc[ma][na][half * 2 + 0] + bx;
                const float vy = acc[ma][na][half * 2 + 1] + by;
                if (z == 0) {
                    P_Q[((size_t)(bb * H_ + hh) * S_ + ss) * DW + (dd >> 1)] =
                        h2pack(vx * scale, vy * scale);
                } else if (z == 1) {
                    P_KH[((size_t)(bb * H_ + hh) * S_ + ss) * DW + (dd >> 1)] =
                        h2pack(vx, vy);
                } else {
                    const size_t vi = ((size_t)(bb * H_ + hh) * D_ + dd) * S_ + ss;
                    P_VH[vi]      = __half_as_ushort(__float2half_rn(vx));
                    P_VH[vi + S_] = __half_as_ushort(__float2half_rn(vy));
                }
            }
        }
    }
}

// ---------------------------------------------------------------------------
// Flash attention: 64-key tiles (16 tiles), Q frags hoisted to registers,
// fp16 mma + exp2 softmax, cp.async double-buffered K/V.
// dyn smem: sQ 64x44 | sK 2x64x44 | sVt 2x72x36 = 54528 B.
// grid (S/64, H, B), 128 threads.
// ---------------------------------------------------------------------------
__global__ void __launch_bounds__(128) attn_kernel()
{
    extern __shared__ uint32_t smdyn[];
    uint32_t* sQ  = smdyn;             // 2816 words
    uint32_t* sK  = smdyn + 2816;      // 2 x 2816
    uint32_t* sVt = smdyn + 8448;      // 2 x 2592

    const int qt = blockIdx.x, h = blockIdx.y, b = blockIdx.z;
    const int tid = threadIdx.x;
    const int lane = tid & 31, warp = tid >> 5;
    const int g = lane >> 2, tg = lane & 3;

    const uint32_t sQb = smem_u32(sQ);
    const uint32_t sKb = smem_u32(sK);
    const uint32_t sVb = smem_u32(sVt);

    const uint32_t* Qg = P_Q  + ((size_t)(b * H_ + h) * S_ + qt * 64) * DW;
    const uint32_t* Kg = P_KH + (size_t)(b * H_ + h) * S_ * DW;
    const uint16_t* Vg = P_VH + (size_t)(b * H_ + h) * D_ * S_;

    // zero k-pad words (36..39) of sQ and both sK buffers (stride 44)
    for (int i = tid; i < 768; i += 128) {
        if (i < 256) {
            const int r = i >> 2;
            sQ[r * 44 + 36 + (i & 3)] = 0;
        } else {
            const int j = i - 256, r = j >> 2;
            sK[r * 44 + 36 + (j & 3)] = 0;
        }
    }

    auto load_tile = [&](int t, int buf) {
        const int kt = t * 64;
        const uint32_t dK = sKb + (uint32_t)buf * (64 * 44 * 4);
        const uint32_t dV = sVb + (uint32_t)buf * (72 * 36 * 4);
#pragma unroll
        for (int j = 0; j < 5; j++) {              // K: 64 rows x 9 chunks = 576
            const int idx = j * 128 + tid;
            if (idx < 576) {
                const int r = idx / 9, c = (idx % 9) * 4;
                cpa16(dK + (r * 44 + c) * 4, Kg + (size_t)(kt + r) * DW + c);
            }
        }
#pragma unroll
        for (int j = 0; j < 5; j++) {              // V: 72 rows x 8 chunks = 576
            const int idx = j * 128 + tid;
            if (idx < 576) {
                const int d = idx >> 3, c = idx & 7;
                cpa16(dV + (d * 36 + c * 4) * 4, Vg + (size_t)d * S_ + kt + c * 8);
            }
        }
        asm volatile("cp.async.commit_group;" ::: "memory");
    };

    // prologue: Q (64 rows x 9 chunks = 576, folded into group 0) + tiles 0,1
#pragma unroll
    for (int j = 0; j < 5; j++) {
        const int idx = j * 128 + tid;
        if (idx < 576) {
            const int r = idx / 9, c = (idx % 9) * 4;
            cpa16(sQb + (r * 44 + c) * 4, Qg + (size_t)r * DW + c);
        }
    }
    load_tile(0, 0);
    load_tile(1, 1);

    float O[9][4];
#pragma unroll
    for (int i = 0; i < 9; i++)
#pragma unroll
        for (int j = 0; j < 4; j++) O[i][j] = 0.0f;
    float m0 = -3.0e38f, m1 = -3.0e38f, l0 = 0.0f, l1 = 0.0f;
    const int m0r = warp * 16 + g;

    uint32_t qf[5][4];   // Q fragments, loaded once at t=0

    for (int t = 0; t < 16; t++) {
        if (t + 1 < 16)
            asm volatile("cp.async.wait_group 1;" ::: "memory");
        else
            asm volatile("cp.async.wait_group 0;" ::: "memory");
        __syncthreads();

        if (t == 0) {
#pragma unroll
            for (int ks = 0; ks < 5; ks++) {
                const int kk = ks * 8 + tg;
                qf[ks][0] = sQ[m0r * 44 + kk];
                qf[ks][1] = sQ[(m0r + 8) * 44 + kk];
                qf[ks][2] = sQ[m0r * 44 + kk + 4];
                qf[ks][3] = sQ[(m0r + 8) * 44 + kk + 4];
            }
        }

        const uint32_t* bK = sK + (t & 1) * (64 * 44);
        const uint32_t* bV = sVt + (t & 1) * (72 * 36);

        // S = Q K^T over 64 keys (8 n-blocks), k = 80 halves (5 k16 steps)
        float Sc[8][4];
#pragma unroll
        for (int i = 0; i < 8; i++)
#pragma unroll
            for (int j = 0; j < 4; j++) Sc[i][j] = 0.0f;
#pragma unroll
        for (int ks = 0; ks < 5; ks++) {
            const int kk = ks * 8 + tg;
#pragma unroll
            for (int na = 0; na < 8; na++) {
                const uint32_t b0 = bK[(na * 8 + g) * 44 + kk];
                const uint32_t b1 = bK[(na * 8 + g) * 44 + kk + 4];
                mma_f16(Sc[na], qf[ks][0], qf[ks][1], qf[ks][2], qf[ks][3],
                        b0, b1);
            }
        }

        // online softmax (exp2 domain)
        float mx0 = -3.0e38f, mx1 = -3.0e38f;
#pragma unroll
        for (int na = 0; na < 8; na++) {
            mx0 = fmaxf(mx0, fmaxf(Sc[na][0], Sc[na][1]));
            mx1 = fmaxf(mx1, fmaxf(Sc[na][2], Sc[na][3]));
        }
        mx0 = fmaxf(mx0, __shfl_xor_sync(0xffffffffu, mx0, 1));
        mx0 = fmaxf(mx0, __shfl_xor_sync(0xffffffffu, mx0, 2));
        mx1 = fmaxf(mx1, __shfl_xor_sync(0xffffffffu, mx1, 1));
        mx1 = fmaxf(mx1, __shfl_xor_sync(0xffffffffu, mx1, 2));

        const float nm0 = fmaxf(m0, mx0), nm1 = fmaxf(m1, mx1);
        const float al0 = ex2f(m0 - nm0), al1 = ex2f(m1 - nm1);
        float s0 = 0.0f, s1 = 0.0f;
#pragma unroll
        for (int na = 0; na < 8; na++) {
            Sc[na][0] = ex2f(Sc[na][0] - nm0);
            Sc[na][1] = ex2f(Sc[na][1] - nm0);
            Sc[na][2] = ex2f(Sc[na][2] - nm1);
            Sc[na][3] = ex2f(Sc[na][3] - nm1);
            s0 += Sc[na][0] + Sc[na][1];
            s1 += Sc[na][2] + Sc[na][3];
        }
        s0 += __shfl_xor_sync(0xffffffffu, s0, 1);
        s0 += __shfl_xor_sync(0xffffffffu, s0, 2);
        s1 += __shfl_xor_sync(0xffffffffu, s1, 1);
        s1 += __shfl_xor_sync(0xffffffffu, s1, 2);
        l0 = l0 * al0 + s0;
        l1 = l1 * al1 + s1;
        m0 = nm0; m1 = nm1;
#pragma unroll
        for (int na = 0; na < 9; na++) {
            O[na][0] *= al0; O[na][1] *= al0;
            O[na][2] *= al1; O[na][3] *= al1;
        }

        // O += P V : A-frags straight from S accumulators; k = 64 keys (4 k16 steps)
#pragma unroll
        for (int ks = 0; ks < 4; ks++) {
            const uint32_t a0 = h2pack(Sc[2 * ks][0],     Sc[2 * ks][1]);
            const uint32_t a1 = h2pack(Sc[2 * ks][2],     Sc[2 * ks][3]);
            const uint32_t a2 = h2pack(Sc[2 * ks + 1][0], Sc[2 * ks + 1][1]);
            const uint32_t a3 = h2pack(Sc[2 * ks + 1][2], Sc[2 * ks + 1][3]);
            const int kk = ks * 8 + tg;
#pragma unroll
            for (int na = 0; na < 9; na++) {
                const uint32_t b0 = bV[(na * 8 + g) * 36 + kk];
                const uint32_t b1 = bV[(na * 8 + g) * 36 + kk + 4];
                mma_f16(O[na], a0, a1, a2, a3, b0, b1);
            }
        }

        __syncthreads();
        if (t + 2 < 16) load_tile(t + 2, t & 1);
    }

    // epilogue -> Ah (fp16)
    const float i0 = 1.0f / l0, i1 = 1.0f / l1;
    const int r0 = qt * 64 + warp * 16 + g;
    uint32_t* out0 = P_AH + (size_t)(b * S_ + r0) * EW + h * DW;
    uint32_t* out1 = P_AH + (size_t)(b * S_ + r0 + 8) * EW + h * DW;
#pragma unroll
    for (int na = 0; na < 9; na++) {
        const int cw = na * 4 + tg;
        out0[cw] = h2pack(O[na][0] * i0, O[na][1] * i0);
        out1[cw] = h2pack(O[na][2] * i1, O[na][3] * i1);
    }
}

// ---------------------------------------------------------------------------
// Output projection (fp16 mma): A=Ah, B=owh2, both via 2-stage cp.async.
// grid (9, 64), 256 threads. (Unchanged from R13.)
// ---------------------------------------------------------------------------
#define TQ 72
__global__ void __launch_bounds__(256) out_gemm(const float* __restrict__ bias,
                                                float* __restrict__ outp)
{
    const int rowBase = blockIdx.y * 128;
    const int colBase = blockIdx.x * 128;
    const uint32_t* At = P_AH;
    const uint32_t* Wt = P_OWH;

    __shared__ __align__(16) uint32_t sA[2][128 * 12];
    __shared__ __align__(16) uint32_t sB[2][8 * 136];

    const int tid  = threadIdx.x;
    const int lane = tid & 31, warp = tid >> 5;
    const int wm = warp >> 2, wn = warp & 3;
    const int g = lane >> 2, tg = lane & 3;

    const int rowA = tid >> 1;
    const int kcA  = (tid & 1) * 4;
    const int krB  = tid >> 5;
    const int ncB  = (tid & 31) * 4;

    const uint32_t sA0 = smem_u32(&sA[0][0]);
    const uint32_t sA1 = smem_u32(&sA[1][0]);
    const uint32_t sB0 = smem_u32(&sB[0][0]);
    const uint32_t sB1 = smem_u32(&sB[1][0]);

    float acc[4][4][4];
#pragma unroll
    for (int i = 0; i < 4; i++)
#pragma unroll
        for (int j = 0; j < 4; j++)
#pragma unroll
            for (int l = 0; l < 4; l++) acc[i][j][l] = 0.0f;

    auto load_stage = [&](int t, uint32_t dA, uint32_t dB) {
        cpa16(dA + (rowA * 12 + kcA) * 4,
              At + (size_t)(rowBase + rowA) * EW + t * 8 + kcA);
        cpa16(dB + (krB * 136 + ncB) * 4,
              Wt + (size_t)(t * 8 + krB) * E_ + colBase + ncB);
        asm volatile("cp.async.commit_group;" ::: "memory");
    };

    load_stage(0, sA0, sB0);

    for (int t = 0; t < TQ; t++) {
        asm volatile("cp.async.wait_group 0;" ::: "memory");
        __syncthreads();
        if (t + 1 < TQ)
            load_stage(t + 1, ((t + 1) & 1) ? sA1 : sA0, ((t + 1) & 1) ? sB1 : sB0);

        const uint32_t* As = sA[t & 1];
        const uint32_t* Bv = sB[t & 1];
        uint32_t af[4][4], bf[4][2];
#pragma unroll
        for (int ma = 0; ma < 4; ma++) {
            const int m0 = wm * 64 + ma * 16 + g;
            af[ma][0] = As[m0 * 12 + tg];
            af[ma][1] = As[(m0 + 8) * 12 + tg];
            af[ma][2] = As[m0 * 12 + tg + 4];
            af[ma][3] = As[(m0 + 8) * 12 + tg + 4];
        }
#pragma unroll
        for (int na = 0; na < 4; na++) {
            const int n0 = wn * 32 + na * 8 + g;
            bf[na][0] = Bv[tg * 136 + n0];
            bf[na][1] = Bv[(tg + 4) * 136 + n0];
        }
#pragma unroll
        for (int ma = 0; ma < 4; ma++)
#pragma unroll
            for (int na = 0; na < 4; na++)
                mma_f16(acc[ma][na], af[ma][0], af[ma][1], af[ma][2],
                        af[ma][3], bf[na][0], bf[na][1]);
    }

#pragma unroll
    for (int ma = 0; ma < 4; ma++) {
#pragma unroll
        for (int na = 0; na < 4; na++) {
            const int c = colBase + wn * 32 + na * 8 + 2 * tg;
            const float bx = bias[c];
            const float by = bias[c + 1];
#pragma unroll
            for (int half = 0; half < 2; half++) {
                const int r = rowBase + wm * 64 + ma * 16 + g + half * 8;
                float2 ov;
                ov.x = acc[ma][na][half * 2 + 0] + bx;
                ov.y = acc[ma][na][half * 2 + 1] + by;
                *(float2*)&outp[(size_t)r * E_ + c] = ov;
            }
        }
    }
}

// ---------------------------------------------------------------------------
extern "C" void kernel_launch(void* const* d_in, const int* in_sizes, int n_in,
                              void* d_out, int out_size)
{
    const float* q    = (const float*)d_in[0];
    const float* k    = (const float*)d_in[1];
    const float* v    = (const float*)d_in[2];
    const float* W    = (const float*)d_in[3];
    const float* bias = (const float*)d_in[4];
    const float* ow   = (const float*)d_in[5];
    const float* ob   = (const float*)d_in[6];
    float* out = (float*)d_out;

    cudaFuncSetAttribute(attn_kernel,
                         cudaFuncAttributeMaxDynamicSharedMemorySize, 54528);

    packW<<<(EW * (W3E / 4) + 255) / 256, 256>>>(W, OFF_W, W3E, W3E / 4,
                                                 EW * (W3E / 4));
    packW<<<(EW * (E_ / 4) + 255) / 256, 256>>>(ow, OFF_OW, E_, E_ / 4,
                                                EW * (E_ / 4));

    qkv_gemm<<<dim3(E_ / 128, NROW / 128, 3), 256>>>(q, k, v, bias);

    attn_kernel<<<dim3(S_ / 64, H_, B_), 128, 54528>>>();

    out_gemm<<<dim3(E_ / 128, NROW / 128), 256>>>(ob, out);
}

// round 15
// speedup vs baseline: 8.1405x; 1.0549x over previous
#include <cuda_runtime.h>
#include <cuda_fp16.h>
#include <cstdint>

#define B_   8
#define S_   1024
#define E_   1152
#define H_   16
#define D_   72
#define NROW (B_ * S_)
#define W3E  (3 * E_)
#define CH_  (B_ * H_ * S_ * D_)   // 9437184
#define EW   (E_ / 2)              // 576 h2-words per embed row
#define DW   (D_ / 2)              // 36 h2-words per head row

// ------- device scratch: EXACT proven shape (single 144 MiB pool) -------
__device__ uint32_t g_pool[4ull * CH_];

#define OFF_W   (2ull * CH_)
#define OFF_OW  (2ull * CH_ + 1990656ull)
#define P_Q     (g_pool)
#define P_KH    (g_pool + (size_t)CH_ / 2)
#define P_VH    ((uint16_t*)(g_pool + (size_t)CH_))
#define P_AH    (g_pool + 3ull * CH_ / 2)
#define P_WH    (g_pool + OFF_W)
#define P_OWH   (g_pool + OFF_OW)

// ---------------- helpers ----------------
__device__ __forceinline__ uint32_t h2pack(float lo, float hi) {
    uint32_t r;
    asm("cvt.rn.f16x2.f32 %0, %1, %2;" : "=r"(r) : "f"(hi), "f"(lo));
    return r;
}
__device__ __forceinline__ float ex2f(float x) {
    float y;
    asm("ex2.approx.f32 %0, %1;" : "=f"(y) : "f"(x));
    return y;
}
__device__ __forceinline__ uint32_t smem_u32(const void* p) {
    uint32_t a;
    asm("{ .reg .u64 t; cvta.to.shared.u64 t, %1; cvt.u32.u64 %0, t; }"
        : "=r"(a) : "l"(p));
    return a;
}
__device__ __forceinline__ void cpa16(uint32_t s, const void* g) {
    asm volatile("cp.async.cg.shared.global [%0], [%1], 16;"
                 :: "r"(s), "l"(g) : "memory");
}
__device__ __forceinline__ void mma_f16(float (&c)[4],
    uint32_t a0, uint32_t a1, uint32_t a2, uint32_t a3,
    uint32_t b0, uint32_t b1)
{
    asm volatile(
        "mma.sync.aligned.m16n8k16.row.col.f32.f16.f16.f32 "
        "{%0,%1,%2,%3}, {%4,%5,%6,%7}, {%8,%9}, {%0,%1,%2,%3};\n"
        : "+f"(c[0]), "+f"(c[1]), "+f"(c[2]), "+f"(c[3])
        : "r"(a0), "r"(a1), "r"(a2), "r"(a3), "r"(b0), "r"(b1));
}

// ---------------------------------------------------------------------------
// Weight pack: fp32 [K][N] -> h2 words [kw][N] at pool word offset.
// ---------------------------------------------------------------------------
__global__ void packW(const float* __restrict__ src, size_t dst_off,
                      int ncols, int n4c, int total4) {
    const int i = blockIdx.x * blockDim.x + threadIdx.x;
    if (i >= total4) return;
    uint32_t* dst = g_pool + dst_off;
    const int kw = i / n4c, n = (i - kw * n4c) * 4;
    const float4 lo = *(const float4*)&src[(size_t)(2 * kw) * ncols + n];
    const float4 hi = *(const float4*)&src[(size_t)(2 * kw + 1) * ncols + n];
    uint4 o;
    o.x = h2pack(lo.x, hi.x);
    o.y = h2pack(lo.y, hi.y);
    o.z = h2pack(lo.z, hi.z);
    o.w = h2pack(lo.w, hi.w);
    ((uint4*)dst)[i] = o;
}

// ---------------------------------------------------------------------------
// QKV GEMM (fp16 mma): k-tile = 32 halves (16 words), 36 iterations. (R14, proven)
// grid (9, 64, 3), 256 threads (8 warps as 2m x 4n, warp tile 64x32).
// ---------------------------------------------------------------------------
#define TQ2 36

__global__ void __launch_bounds__(256) qkv_gemm(
    const float* __restrict__ q, const float* __restrict__ k,
    const float* __restrict__ v, const float* __restrict__ bias)
{
    const int z = blockIdx.z;
    const float* X = (z == 0) ? q : (z == 1) ? k : v;
    const uint32_t* Wt = P_WH;

    const int rowBase = blockIdx.y * 128;
    const int colBase = blockIdx.x * 128;
    const int wcol0   = z * E_ + colBase;

    __shared__ __align__(16) uint32_t sA[2][128 * 20];
    __shared__ __align__(16) uint32_t sB[3][16 * 136];

    const int tid  = threadIdx.x;
    const int lane = tid & 31, warp = tid >> 5;
    const int wm = warp >> 2, wn = warp & 3;
    const int g = lane >> 2, tg = lane & 3;

    const int rowA = tid >> 1;          // 0..127
    const int kcA  = (tid & 1) * 8;     // word col 0 or 8
    const int krB  = tid >> 5;          // 0..7 (and +8)
    const int ncB  = (tid & 31) * 4;

    const uint32_t sBb = smem_u32(&sB[0][0]);

    float acc[4][4][4];
#pragma unroll
    for (int i = 0; i < 4; i++)
#pragma unroll
        for (int j = 0; j < 4; j++)
#pragma unroll
            for (int l = 0; l < 4; l++) acc[i][j][l] = 0.0f;

    float4 a0v, a1v, a2v, a3v;

    auto loadA_g = [&](int t) {
        const size_t fb = (size_t)(rowBase + rowA) * E_ + t * 32 + (tid & 1) * 16;
        a0v = *(const float4*)&X[fb];
        a1v = *(const float4*)&X[fb + 4];
        a2v = *(const float4*)&X[fb + 8];
        a3v = *(const float4*)&X[fb + 12];
    };
    auto storeA_s = [&](int buf) {
        uint32_t* A = sA[buf];
        *(uint4*)&A[rowA * 20 + kcA] =
            make_uint4(h2pack(a0v.x, a0v.y), h2pack(a0v.z, a0v.w),
                       h2pack(a1v.x, a1v.y), h2pack(a1v.z, a1v.w));
        *(uint4*)&A[rowA * 20 + kcA + 4] =
            make_uint4(h2pack(a2v.x, a2v.y), h2pack(a2v.z, a2v.w),
                       h2pack(a3v.x, a3v.y), h2pack(a3v.z, a3v.w));
    };
    auto loadB = [&](int t) {
        const uint32_t dB = sBb + (uint32_t)(t % 3) * (16 * 136 * 4);
        cpa16(dB + (krB * 136 + ncB) * 4,
              Wt + (size_t)(t * 16 + krB) * W3E + wcol0 + ncB);
        cpa16(dB + ((krB + 8) * 136 + ncB) * 4,
              Wt + (size_t)(t * 16 + krB + 8) * W3E + wcol0 + ncB);
        asm volatile("cp.async.commit_group;" ::: "memory");
    };

    loadA_g(0);
    storeA_s(0);
    loadB(0);
    loadB(1);

    for (int t = 0; t < TQ2; t++) {
        if (t + 1 < TQ2) loadA_g(t + 1);
        if (t + 1 < TQ2)
            asm volatile("cp.async.wait_group 1;" ::: "memory");
        else
            asm volatile("cp.async.wait_group 0;" ::: "memory");
        __syncthreads();
        if (t + 2 < TQ2) loadB(t + 2);

        const uint32_t* As = sA[t & 1];
        const uint32_t* Bv = sB[t % 3];
#pragma unroll
        for (int ks = 0; ks < 2; ks++) {
            const int kk = ks * 8 + tg;
            uint32_t af[4][4], bf[4][2];
#pragma unroll
            for (int ma = 0; ma < 4; ma++) {
                const int m0 = wm * 64 + ma * 16 + g;
                af[ma][0] = As[m0 * 20 + kk];
                af[ma][1] = As[(m0 + 8) * 20 + kk];
                af[ma][2] = As[m0 * 20 + kk + 4];
                af[ma][3] = As[(m0 + 8) * 20 + kk + 4];
            }
#pragma unroll
            for (int na = 0; na < 4; na++) {
                const int n0 = wn * 32 + na * 8 + g;
                bf[na][0] = Bv[kk * 136 + n0];
                bf[na][1] = Bv[(kk + 4) * 136 + n0];
            }
#pragma unroll
            for (int ma = 0; ma < 4; ma++)
#pragma unroll
                for (int na = 0; na < 4; na++)
                    mma_f16(acc[ma][na], af[ma][0], af[ma][1], af[ma][2],
                            af[ma][3], bf[na][0], bf[na][1]);
        }

        if (t + 1 < TQ2) storeA_s((t + 1) & 1);
    }

    const float scale = 0.17002325737443355f;  // 72^-0.5 * log2(e)
#pragma unroll
    for (int ma = 0; ma < 4; ma++) {
#pragma unroll
        for (int na = 0; na < 4; na++) {
            const int c  = colBase + wn * 32 + na * 8 + 2 * tg;
            const float bx = bias[z * E_ + c];
            const float by = bias[z * E_ + c + 1];
            const int hh = c / D_;
            const int dd = c - hh * D_;
#pragma unroll
            for (int half = 0; half < 2; half++) {
                const int r = rowBase + wm * 64 + ma * 16 + g + half * 8;
                const int bb = r >> 10, ss = r & 1023;
                const float vx = acc[ma][na][half * 2 + 0] + bx;
                const float vy = acc[ma][na][half * 2 + 1] + by;
                if (z == 0) {
                    P_Q[((size_t)(bb * H_ + hh) * S_ + ss) * DW + (dd >> 1)] =
                        h2pack(vx * scale, vy * scale);
                } else if (z == 1) {
                    P_KH[((size_t)(bb * H_ + hh) * S_ + ss) * DW + (dd >> 1)] =
                        h2pack(vx, vy);
                } else {
                    const size_t vi = ((size_t)(bb * H_ + hh) * D_ + dd) * S_ + ss;
                    P_VH[vi]      = __half_as_ushort(__float2half_rn(vx));
                    P_VH[vi + S_] = __half_as_ushort(__float2half_rn(vy));
                }
            }
        }
    }
}

// ---------------------------------------------------------------------------
// Flash attention: R13-exact (32-key tiles, static 34 KB smem, measured 189 us).
// grid (S/64, H, B), 128 threads.
// ---------------------------------------------------------------------------
__global__ void __launch_bounds__(128) attn_kernel()
{
    __shared__ __align__(16) uint32_t sQ[64 * 44];
    __shared__ __align__(16) uint32_t sK[2 * 32 * 44];
    __shared__ __align__(16) uint32_t sVt[2 * 72 * 20];

    const int qt = blockIdx.x, h = blockIdx.y, b = blockIdx.z;
    const int tid = threadIdx.x;
    const int lane = tid & 31, warp = tid >> 5;
    const int g = lane >> 2, tg = lane & 3;

    const uint32_t sQb = smem_u32(sQ);
    const uint32_t sKb = smem_u32(sK);
    const uint32_t sVb = smem_u32(sVt);

    const uint32_t* Qg = P_Q  + ((size_t)(b * H_ + h) * S_ + qt * 64) * DW;
    const uint32_t* Kg = P_KH + (size_t)(b * H_ + h) * S_ * DW;
    const uint16_t* Vg = P_VH + (size_t)(b * H_ + h) * D_ * S_;

    // zero k-pad words (36..39) of sQ and both sK buffers
    for (int i = tid; i < 512; i += 128) {
        const int r = (i & 255) >> 2, w = 36 + (i & 3);
        if (i < 256) sQ[r * 44 + w] = 0;
        else         sK[r * 44 + w] = 0;
    }

    auto load_tile = [&](int t, int buf) {
        const int kt = t * 32;
        const uint32_t dK = sKb + (uint32_t)buf * (32 * 44 * 4);
        const uint32_t dV = sVb + (uint32_t)buf * (72 * 20 * 4);
#pragma unroll
        for (int j = 0; j < 3; j++) {              // K: 32 rows x 9 chunks = 288
            const int idx = j * 128 + tid;
            if (idx < 288) {
                const int r = idx / 9, c = (idx % 9) * 4;
                cpa16(dK + (r * 44 + c) * 4, Kg + (size_t)(kt + r) * DW + c);
            }
        }
#pragma unroll
        for (int j = 0; j < 3; j++) {              // V: 72 rows x 4 chunks = 288
            const int idx = j * 128 + tid;
            if (idx < 288) {
                const int d = idx >> 2, c = idx & 3;
                cpa16(dV + (d * 20 + c * 4) * 4, Vg + (size_t)d * S_ + kt + c * 8);
            }
        }
        asm volatile("cp.async.commit_group;" ::: "memory");
    };

    // prologue: Q (64 rows x 9 chunks = 576, folded into group 0) + tiles 0,1
#pragma unroll
    for (int j = 0; j < 5; j++) {
        const int idx = j * 128 + tid;
        if (idx < 576) {
            const int r = idx / 9, c = (idx % 9) * 4;
            cpa16(sQb + (r * 44 + c) * 4, Qg + (size_t)r * DW + c);
        }
    }
    load_tile(0, 0);
    load_tile(1, 1);

    float O[9][4];
#pragma unroll
    for (int i = 0; i < 9; i++)
#pragma unroll
        for (int j = 0; j < 4; j++) O[i][j] = 0.0f;
    float m0 = -3.0e38f, m1 = -3.0e38f, l0 = 0.0f, l1 = 0.0f;
    const int m0r = warp * 16 + g;

    for (int t = 0; t < 32; t++) {
        if (t + 1 < 32)
            asm volatile("cp.async.wait_group 1;" ::: "memory");
        else
            asm volatile("cp.async.wait_group 0;" ::: "memory");
        __syncthreads();

        const uint32_t* bK = sK + (t & 1) * (32 * 44);
        const uint32_t* bV = sVt + (t & 1) * (72 * 20);

        // S = Q K^T (k = 80 halves = 5 k16 steps; pad zeroed)
        float Sc[4][4];
#pragma unroll
        for (int i = 0; i < 4; i++)
#pragma unroll
            for (int j = 0; j < 4; j++) Sc[i][j] = 0.0f;
#pragma unroll
        for (int ks = 0; ks < 5; ks++) {
            const int kk = ks * 8 + tg;
            const uint32_t a0 = sQ[m0r * 44 + kk];
            const uint32_t a1 = sQ[(m0r + 8) * 44 + kk];
            const uint32_t a2 = sQ[m0r * 44 + kk + 4];
            const uint32_t a3 = sQ[(m0r + 8) * 44 + kk + 4];
#pragma unroll
            for (int na = 0; na < 4; na++) {
                const uint32_t b0 = bK[(na * 8 + g) * 44 + kk];
                const uint32_t b1 = bK[(na * 8 + g) * 44 + kk + 4];
                mma_f16(Sc[na], a0, a1, a2, a3, b0, b1);
            }
        }

        // online softmax (exp2 domain)
        float mx0 = -3.0e38f, mx1 = -3.0e38f;
#pragma unroll
        for (int na = 0; na < 4; na++) {
            mx0 = fmaxf(mx0, fmaxf(Sc[na][0], Sc[na][1]));
            mx1 = fmaxf(mx1, fmaxf(Sc[na][2], Sc[na][3]));
        }
        mx0 = fmaxf(mx0, __shfl_xor_sync(0xffffffffu, mx0, 1));
        mx0 = fmaxf(mx0, __shfl_xor_sync(0xffffffffu, mx0, 2));
        mx1 = fmaxf(mx1, __shfl_xor_sync(0xffffffffu, mx1, 1));
        mx1 = fmaxf(mx1, __shfl_xor_sync(0xffffffffu, mx1, 2));

        const float nm0 = fmaxf(m0, mx0), nm1 = fmaxf(m1, mx1);
        const float al0 = ex2f(m0 - nm0), al1 = ex2f(m1 - nm1);
        float s0 = 0.0f, s1 = 0.0f;
#pragma unroll
        for (int na = 0; na < 4; na++) {
            Sc[na][0] = ex2f(Sc[na][0] - nm0);
            Sc[na][1] = ex2f(Sc[na][1] - nm0);
            Sc[na][2] = ex2f(Sc[na][2] - nm1);
            Sc[na][3] = ex2f(Sc[na][3] - nm1);
            s0 += Sc[na][0] + Sc[na][1];
            s1 += Sc[na][2] + Sc[na][3];
        }
        s0 += __shfl_xor_sync(0xffffffffu, s0, 1);
        s0 += __shfl_xor_sync(0xffffffffu, s0, 2);
        s1 += __shfl_xor_sync(0xffffffffu, s1, 1);
        s1 += __shfl_xor_sync(0xffffffffu, s1, 2);
        l0 = l0 * al0 + s0;
        l1 = l1 * al1 + s1;
        m0 = nm0; m1 = nm1;
#pragma unroll
        for (int na = 0; na < 9; na++) {
            O[na][0] *= al0; O[na][1] *= al0;
            O[na][2] *= al1; O[na][3] *= al1;
        }

        // O += P V : A-frags straight from S accumulators (no shuffles)
#pragma unroll
        for (int ks = 0; ks < 2; ks++) {
            const uint32_t a0 = h2pack(Sc[2 * ks][0],     Sc[2 * ks][1]);
            const uint32_t a1 = h2pack(Sc[2 * ks][2],     Sc[2 * ks][3]);
            const uint32_t a2 = h2pack(Sc[2 * ks + 1][0], Sc[2 * ks + 1][1]);
            const uint32_t a3 = h2pack(Sc[2 * ks + 1][2], Sc[2 * ks + 1][3]);
            const int kk = ks * 8 + tg;
#pragma unroll
            for (int na = 0; na < 9; na++) {
                const uint32_t b0 = bV[(na * 8 + g) * 20 + kk];
                const uint32_t b1 = bV[(na * 8 + g) * 20 + kk + 4];
                mma_f16(O[na], a0, a1, a2, a3, b0, b1);
            }
        }

        __syncthreads();
        if (t + 2 < 32) load_tile(t + 2, t & 1);
    }

    // epilogue -> Ah (fp16)
    const float i0 = 1.0f / l0, i1 = 1.0f / l1;
    const int r0 = qt * 64 + warp * 16 + g;
    uint32_t* out0 = P_AH + (size_t)(b * S_ + r0) * EW + h * DW;
    uint32_t* out1 = P_AH + (size_t)(b * S_ + r0 + 8) * EW + h * DW;
#pragma unroll
    for (int na = 0; na < 9; na++) {
        const int cw = na * 4 + tg;
        out0[cw] = h2pack(O[na][0] * i0, O[na][1] * i0);
        out1[cw] = h2pack(O[na][2] * i1, O[na][3] * i1);
    }
}

// ---------------------------------------------------------------------------
// Output projection (fp16 mma): now 3-stage cp.async with wait_group 1.
// grid (9, 64), 256 threads.
// ---------------------------------------------------------------------------
#define TQ 72
__global__ void __launch_bounds__(256) out_gemm(const float* __restrict__ bias,
                                                float* __restrict__ outp)
{
    const int rowBase = blockIdx.y * 128;
    const int colBase = blockIdx.x * 128;
    const uint32_t* At = P_AH;
    const uint32_t* Wt = P_OWH;

    __shared__ __align__(16) uint32_t sA[3][128 * 12];
    __shared__ __align__(16) uint32_t sB[3][8 * 136];

    const int tid  = threadIdx.x;
    const int lane = tid & 31, warp = tid >> 5;
    const int wm = warp >> 2, wn = warp & 3;
    const int g = lane >> 2, tg = lane & 3;

    const int rowA = tid >> 1;
    const int kcA  = (tid & 1) * 4;
    const int krB  = tid >> 5;
    const int ncB  = (tid & 31) * 4;

    const uint32_t sAb = smem_u32(&sA[0][0]);
    const uint32_t sBb = smem_u32(&sB[0][0]);

    float acc[4][4][4];
#pragma unroll
    for (int i = 0; i < 4; i++)
#pragma unroll
        for (int j = 0; j < 4; j++)
#pragma unroll
            for (int l = 0; l < 4; l++) acc[i][j][l] = 0.0f;

    auto load_stage = [&](int t) {
        const uint32_t dA = sAb + (uint32_t)(t % 3) * (128 * 12 * 4);
        const uint32_t dB = sBb + (uint32_t)(t % 3) * (8 * 136 * 4);
        cpa16(dA + (rowA * 12 + kcA) * 4,
              At + (size_t)(rowBase + rowA) * EW + t * 8 + kcA);
        cpa16(dB + (krB * 136 + ncB) * 4,
              Wt + (size_t)(t * 8 + krB) * E_ + colBase + ncB);
        asm volatile("cp.async.commit_group;" ::: "memory");
    };

    load_stage(0);
    load_stage(1);

    for (int t = 0; t < TQ; t++) {
        if (t + 1 < TQ)
            asm volatile("cp.async.wait_group 1;" ::: "memory");
        else
            asm volatile("cp.async.wait_group 0;" ::: "memory");
        __syncthreads();
        if (t + 2 < TQ) load_stage(t + 2);

        const uint32_t* As = sA[t % 3];
        const uint32_t* Bv = sB[t % 3];
        uint32_t af[4][4], bf[4][2];
#pragma unroll
        for (int ma = 0; ma < 4; ma++) {
            const int m0 = wm * 64 + ma * 16 + g;
            af[ma][0] = As[m0 * 12 + tg];
            af[ma][1] = As[(m0 + 8) * 12 + tg];
            af[ma][2] = As[m0 * 12 + tg + 4];
            af[ma][3] = As[(m0 + 8) * 12 + tg + 4];
        }
#pragma unroll
        for (int na = 0; na < 4; na++) {
            const int n0 = wn * 32 + na * 8 + g;
            bf[na][0] = Bv[tg * 136 + n0];
            bf[na][1] = Bv[(tg + 4) * 136 + n0];
        }
#pragma unroll
        for (int ma = 0; ma < 4; ma++)
#pragma unroll
            for (int na = 0; na < 4; na++)
                mma_f16(acc[ma][na], af[ma][0], af[ma][1], af[ma][2],
                        af[ma][3], bf[na][0], bf[na][1]);
    }

#pragma unroll
    for (int ma = 0; ma < 4; ma++) {
#pragma unroll
        for (int na = 0; na < 4; na++) {
            const int c = colBase + wn * 32 + na * 8 + 2 * tg;
            const float bx = bias[c];
            const float by = bias[c + 1];
#pragma unroll
            for (int half = 0; half < 2; half++) {
                const int r = rowBase + wm * 64 + ma * 16 + g + half * 8;
                float2 ov;
                ov.x = acc[ma][na][half * 2 + 0] + bx;
                ov.y = acc[ma][na][half * 2 + 1] + by;
                *(float2*)&outp[(size_t)r * E_ + c] = ov;
            }
        }
    }
}

// ---------------------------------------------------------------------------
extern "C" void kernel_launch(void* const* d_in, const int* in_sizes, int n_in,
                              void* d_out, int out_size)
{
    const float* q    = (const float*)d_in[0];
    const float* k    = (const float*)d_in[1];
    const float* v    = (const float*)d_in[2];
    const float* W    = (const float*)d_in[3];
    const float* bias = (const float*)d_in[4];
    const float* ow   = (const float*)d_in[5];
    const float* ob   = (const float*)d_in[6];
    float* out = (float*)d_out;

    packW<<<(EW * (W3E / 4) + 255) / 256, 256>>>(W, OFF_W, W3E, W3E / 4,
                                                 EW * (W3E / 4));
    packW<<<(EW * (E_ / 4) + 255) / 256, 256>>>(ow, OFF_OW, E_, E_ / 4,
                                                EW * (E_ / 4));

    qkv_gemm<<<dim3(E_ / 128, NROW / 128, 3), 256>>>(q, k, v, bias);

    attn_kernel<<<dim3(S_ / 64, H_, B_), 128>>>();

    out_gemm<<<dim3(E_ / 128, NROW / 128), 256>>>(ob, out);
}

// round 16
// speedup vs baseline: 8.6356x; 1.0608x over previous
#include <cuda_runtime.h>
#include <cuda_fp16.h>
#include <cstdint>

#define B_   8
#define S_   1024
#define E_   1152
#define H_   16
#define D_   72
#define NROW (B_ * S_)
#define W3E  (3 * E_)
#define CH_  (B_ * H_ * S_ * D_)   // 9437184
#define EW   (E_ / 2)              // 576 h2-words per embed row
#define DW   (D_ / 2)              // 36 h2-words per head row
#define XW_  ((size_t)NROW * EW)   // 4718592 words per input tensor

// ------- device scratch: EXACT proven shape (single 144 MiB pool) -------
__device__ uint32_t g_pool[4ull * CH_];

#define OFF_W   (2ull * CH_)
#define OFF_OW  (2ull * CH_ + 1990656ull)
#define OFF_X   (2ull * CH_ + 1990656ull + 663552ull)   // 3*XW_ fits below 4*CH_
#define P_Q     (g_pool)
#define P_KH    (g_pool + (size_t)CH_ / 2)
#define P_VH    ((uint16_t*)(g_pool + (size_t)CH_))
#define P_AH    (g_pool + 3ull * CH_ / 2)
#define P_WH    (g_pool + OFF_W)
#define P_OWH   (g_pool + OFF_OW)
#define P_X     (g_pool + OFF_X)

// ---------------- helpers ----------------
__device__ __forceinline__ uint32_t h2pack(float lo, float hi) {
    uint32_t r;
    asm("cvt.rn.f16x2.f32 %0, %1, %2;" : "=r"(r) : "f"(hi), "f"(lo));
    return r;
}
__device__ __forceinline__ float ex2f(float x) {
    float y;
    asm("ex2.approx.f32 %0, %1;" : "=f"(y) : "f"(x));
    return y;
}
__device__ __forceinline__ uint32_t smem_u32(const void* p) {
    uint32_t a;
    asm("{ .reg .u64 t; cvta.to.shared.u64 t, %1; cvt.u32.u64 %0, t; }"
        : "=r"(a) : "l"(p));
    return a;
}
__device__ __forceinline__ void cpa16(uint32_t s, const void* g) {
    asm volatile("cp.async.cg.shared.global [%0], [%1], 16;"
                 :: "r"(s), "l"(g) : "memory");
}
__device__ __forceinline__ void mma_f16(float (&c)[4],
    uint32_t a0, uint32_t a1, uint32_t a2, uint32_t a3,
    uint32_t b0, uint32_t b1)
{
    asm volatile(
        "mma.sync.aligned.m16n8k16.row.col.f32.f16.f16.f32 "
        "{%0,%1,%2,%3}, {%4,%5,%6,%7}, {%8,%9}, {%0,%1,%2,%3};\n"
        : "+f"(c[0]), "+f"(c[1]), "+f"(c[2]), "+f"(c[3])
        : "r"(a0), "r"(a1), "r"(a2), "r"(a3), "r"(b0), "r"(b1));
}

// ---------------------------------------------------------------------------
// Weight pack: fp32 [K][N] -> h2 words [kw][N] (pack along K) at pool offset.
// ---------------------------------------------------------------------------
__global__ void packW(const float* __restrict__ src, size_t dst_off,
                      int ncols, int n4c, int total4) {
    const int i = blockIdx.x * blockDim.x + threadIdx.x;
    if (i >= total4) return;
    uint32_t* dst = g_pool + dst_off;
    const int kw = i / n4c, n = (i - kw * n4c) * 4;
    const float4 lo = *(const float4*)&src[(size_t)(2 * kw) * ncols + n];
    const float4 hi = *(const float4*)&src[(size_t)(2 * kw + 1) * ncols + n];
    uint4 o;
    o.x = h2pack(lo.x, hi.x);
    o.y = h2pack(lo.y, hi.y);
    o.z = h2pack(lo.z, hi.z);
    o.w = h2pack(lo.w, hi.w);
    ((uint4*)dst)[i] = o;
}

// ---------------------------------------------------------------------------
// Input pack: fp32 row-major -> fp16x2 words (pack along contiguous dim).
// ---------------------------------------------------------------------------
__global__ void packX(const float4* __restrict__ src, size_t dst_off, int n4) {
    uint4* dst = (uint4*)(g_pool + dst_off);
    for (int i = blockIdx.x * blockDim.x + threadIdx.x; i < n4;
         i += gridDim.x * blockDim.x) {
        const float4 lo = src[2 * i];
        const float4 hi = src[2 * i + 1];
        uint4 o;
        o.x = h2pack(lo.x, lo.y);
        o.y = h2pack(lo.z, lo.w);
        o.z = h2pack(hi.x, hi.y);
        o.w = h2pack(hi.z, hi.w);
        dst[i] = o;
    }
}

// ---------------------------------------------------------------------------
// QKV GEMM (fp16 mma): A and B both fp16 via 3-stage cp.async.
// k-tile = 32 halves (16 words), 36 iterations.
// dyn smem: sA 3x128x20 + sB 3x16x136 = 56832 B.
// grid (9, 64, 3), 256 threads (8 warps as 2m x 4n, warp tile 64x32).
// ---------------------------------------------------------------------------
#define TQ2 36

__global__ void __launch_bounds__(256) qkv_gemm(const float* __restrict__ bias)
{
    extern __shared__ uint32_t smdyn[];
    uint32_t* sA = smdyn;              // 3 x 2560 words
    uint32_t* sB = smdyn + 3 * 2560;   // 3 x 2176 words

    const int z = blockIdx.z;
    const uint32_t* Xh = P_X + (size_t)z * XW_;
    const uint32_t* Wt = P_WH;

    const int rowBase = blockIdx.y * 128;
    const int colBase = blockIdx.x * 128;
    const int wcol0   = z * E_ + colBase;

    const int tid  = threadIdx.x;
    const int lane = tid & 31, warp = tid >> 5;
    const int wm = warp >> 2, wn = warp & 3;
    const int g = lane >> 2, tg = lane & 3;

    const int rowA = tid >> 1;          // 0..127
    const int kcA  = (tid & 1) * 8;     // word col 0 or 8
    const int krB  = tid >> 5;          // 0..7 (and +8)
    const int ncB  = (tid & 31) * 4;

    const uint32_t sAb = smem_u32(sA);
    const uint32_t sBb = smem_u32(sB);

    float acc[4][4][4];
#pragma unroll
    for (int i = 0; i < 4; i++)
#pragma unroll
        for (int j = 0; j < 4; j++)
#pragma unroll
            for (int l = 0; l < 4; l++) acc[i][j][l] = 0.0f;

    auto load_stage = [&](int t) {
        const uint32_t dA = sAb + (uint32_t)(t % 3) * (2560 * 4);
        const uint32_t dB = sBb + (uint32_t)(t % 3) * (2176 * 4);
        const size_t ab = (size_t)(rowBase + rowA) * EW + t * 16 + kcA;
        cpa16(dA + (rowA * 20 + kcA) * 4, Xh + ab);
        cpa16(dA + (rowA * 20 + kcA + 4) * 4, Xh + ab + 4);
        cpa16(dB + (krB * 136 + ncB) * 4,
              Wt + (size_t)(t * 16 + krB) * W3E + wcol0 + ncB);
        cpa16(dB + ((krB + 8) * 136 + ncB) * 4,
              Wt + (size_t)(t * 16 + krB + 8) * W3E + wcol0 + ncB);
        asm volatile("cp.async.commit_group;" ::: "memory");
    };

    load_stage(0);
    load_stage(1);

    for (int t = 0; t < TQ2; t++) {
        if (t + 1 < TQ2)
            asm volatile("cp.async.wait_group 1;" ::: "memory");
        else
            asm volatile("cp.async.wait_group 0;" ::: "memory");
        __syncthreads();
        if (t + 2 < TQ2) load_stage(t + 2);

        const uint32_t* As = sA + (t % 3) * 2560;
        const uint32_t* Bv = sB + (t % 3) * 2176;
#pragma unroll
        for (int ks = 0; ks < 2; ks++) {
            const int kk = ks * 8 + tg;
            uint32_t af[4][4], bf[4][2];
#pragma unroll
            for (int ma = 0; ma < 4; ma++) {
                const int m0 = wm * 64 + ma * 16 + g;
                af[ma][0] = As[m0 * 20 + kk];
                af[ma][1] = As[(m0 + 8) * 20 + kk];
                af[ma][2] = As[m0 * 20 + kk + 4];
                af[ma][3] = As[(m0 + 8) * 20 + kk + 4];
            }
#pragma unroll
            for (int na = 0; na < 4; na++) {
                const int n0 = wn * 32 + na * 8 + g;
                bf[na][0] = Bv[kk * 136 + n0];
                bf[na][1] = Bv[(kk + 4) * 136 + n0];
            }
#pragma unroll
            for (int ma = 0; ma < 4; ma++)
#pragma unroll
                for (int na = 0; na < 4; na++)
                    mma_f16(acc[ma][na], af[ma][0], af[ma][1], af[ma][2],
                            af[ma][3], bf[na][0], bf[na][1]);
        }
    }

    // ---- epilogue: attention-ready fp16 operands (Q folds 72^-0.5 * log2 e) ----
    const float scale = 0.17002325737443355f;
#pragma unroll
    for (int ma = 0; ma < 4; ma++) {
#pragma unroll
        for (int na = 0; na < 4; na++) {
            const int c  = colBase + wn * 32 + na * 8 + 2 * tg;
            const float bx = bias[z * E_ + c];
            const float by = bias[z * E_ + c + 1];
            const int hh = c / D_;
            const int dd = c - hh * D_;
#pragma unroll
            for (int half = 0; half < 2; half++) {
                const int r = rowBase + wm * 64 + ma * 16 + g + half * 8;
                const int bb = r >> 10, ss = r & 1023;
                const float vx = acc[ma][na][half * 2 + 0] + bx;
                const float vy = acc[ma][na][half * 2 + 1] + by;
                if (z == 0) {
                    P_Q[((size_t)(bb * H_ + hh) * S_ + ss) * DW + (dd >> 1)] =
                        h2pack(vx * scale, vy * scale);
                } else if (z == 1) {
                    P_KH[((size_t)(bb * H_ + hh) * S_ + ss) * DW + (dd >> 1)] =
                        h2pack(vx, vy);
                } else {
                    const size_t vi = ((size_t)(bb * H_ + hh) * D_ + dd) * S_ + ss;
                    P_VH[vi]      = __half_as_ushort(__float2half_rn(vx));
                    P_VH[vi + S_] = __half_as_ushort(__float2half_rn(vy));
                }
            }
        }
    }
}

// ---------------------------------------------------------------------------
// Flash attention: R13-exact (32-key tiles, static 34 KB smem, 189 us proven).
// grid (S/64, H, B), 128 threads.
// ---------------------------------------------------------------------------
__global__ void __launch_bounds__(128) attn_kernel()
{
    __shared__ __align__(16) uint32_t sQ[64 * 44];
    __shared__ __align__(16) uint32_t sK[2 * 32 * 44];
    __shared__ __align__(16) uint32_t sVt[2 * 72 * 20];

    const int qt = blockIdx.x, h = blockIdx.y, b = blockIdx.z;
    const int tid = threadIdx.x;
    const int lane = tid & 31, warp = tid >> 5;
    const int g = lane >> 2, tg = lane & 3;

    const uint32_t sQb = smem_u32(sQ);
    const uint32_t sKb = smem_u32(sK);
    const uint32_t sVb = smem_u32(sVt);

    const uint32_t* Qg = P_Q  + ((size_t)(b * H_ + h) * S_ + qt * 64) * DW;
    const uint32_t* Kg = P_KH + (size_t)(b * H_ + h) * S_ * DW;
    const uint16_t* Vg = P_VH + (size_t)(b * H_ + h) * D_ * S_;

    for (int i = tid; i < 512; i += 128) {
        const int r = (i & 255) >> 2, w = 36 + (i & 3);
        if (i < 256) sQ[r * 44 + w] = 0;
        else         sK[r * 44 + w] = 0;
    }

    auto load_tile = [&](int t, int buf) {
        const int kt = t * 32;
        const uint32_t dK = sKb + (uint32_t)buf * (32 * 44 * 4);
        const uint32_t dV = sVb + (uint32_t)buf * (72 * 20 * 4);
#pragma unroll
        for (int j = 0; j < 3; j++) {
            const int idx = j * 128 + tid;
            if (idx < 288) {
                const int r = idx / 9, c = (idx % 9) * 4;
                cpa16(dK + (r * 44 + c) * 4, Kg + (size_t)(kt + r) * DW + c);
            }
        }
#pragma unroll
        for (int j = 0; j < 3; j++) {
            const int idx = j * 128 + tid;
            if (idx < 288) {
                const int d = idx >> 2, c = idx & 3;
                cpa16(dV + (d * 20 + c * 4) * 4, Vg + (size_t)d * S_ + kt + c * 8);
            }
        }
        asm volatile("cp.async.commit_group;" ::: "memory");
    };

#pragma unroll
    for (int j = 0; j < 5; j++) {
        const int idx = j * 128 + tid;
        if (idx < 576) {
            const int r = idx / 9, c = (idx % 9) * 4;
            cpa16(sQb + (r * 44 + c) * 4, Qg + (size_t)r * DW + c);
        }
    }
    load_tile(0, 0);
    load_tile(1, 1);

    float O[9][4];
#pragma unroll
    for (int i = 0; i < 9; i++)
#pragma unroll
        for (int j = 0; j < 4; j++) O[i][j] = 0.0f;
    float m0 = -3.0e38f, m1 = -3.0e38f, l0 = 0.0f, l1 = 0.0f;
    const int m0r = warp * 16 + g;

    for (int t = 0; t < 32; t++) {
        if (t + 1 < 32)
            asm volatile("cp.async.wait_group 1;" ::: "memory");
        else
            asm volatile("cp.async.wait_group 0;" ::: "memory");
        __syncthreads();

        const uint32_t* bK = sK + (t & 1) * (32 * 44);
        const uint32_t* bV = sVt + (t & 1) * (72 * 20);

        float Sc[4][4];
#pragma unroll
        for (int i = 0; i < 4; i++)
#pragma unroll
            for (int j = 0; j < 4; j++) Sc[i][j] = 0.0f;
#pragma unroll
        for (int ks = 0; ks < 5; ks++) {
            const int kk = ks * 8 + tg;
            const uint32_t a0 = sQ[m0r * 44 + kk];
            const uint32_t a1 = sQ[(m0r + 8) * 44 + kk];
            const uint32_t a2 = sQ[m0r * 44 + kk + 4];
            const uint32_t a3 = sQ[(m0r + 8) * 44 + kk + 4];
#pragma unroll
            for (int na = 0; na < 4; na++) {
                const uint32_t b0 = bK[(na * 8 + g) * 44 + kk];
                const uint32_t b1 = bK[(na * 8 + g) * 44 + kk + 4];
                mma_f16(Sc[na], a0, a1, a2, a3, b0, b1);
            }
        }

        float mx0 = -3.0e38f, mx1 = -3.0e38f;
#pragma unroll
        for (int na = 0; na < 4; na++) {
            mx0 = fmaxf(mx0, fmaxf(Sc[na][0], Sc[na][1]));
            mx1 = fmaxf(mx1, fmaxf(Sc[na][2], Sc[na][3]));
        }
        mx0 = fmaxf(mx0, __shfl_xor_sync(0xffffffffu, mx0, 1));
        mx0 = fmaxf(mx0, __shfl_xor_sync(0xffffffffu, mx0, 2));
        mx1 = fmaxf(mx1, __shfl_xor_sync(0xffffffffu, mx1, 1));
        mx1 = fmaxf(mx1, __shfl_xor_sync(0xffffffffu, mx1, 2));

        const float nm0 = fmaxf(m0, mx0), nm1 = fmaxf(m1, mx1);
        const float al0 = ex2f(m0 - nm0), al1 = ex2f(m1 - nm1);
        float s0 = 0.0f, s1 = 0.0f;
#pragma unroll
        for (int na = 0; na < 4; na++) {
            Sc[na][0] = ex2f(Sc[na][0] - nm0);
            Sc[na][1] = ex2f(Sc[na][1] - nm0);
            Sc[na][2] = ex2f(Sc[na][2] - nm1);
            Sc[na][3] = ex2f(Sc[na][3] - nm1);
            s0 += Sc[na][0] + Sc[na][1];
            s1 += Sc[na][2] + Sc[na][3];
        }
        s0 += __shfl_xor_sync(0xffffffffu, s0, 1);
        s0 += __shfl_xor_sync(0xffffffffu, s0, 2);
        s1 += __shfl_xor_sync(0xffffffffu, s1, 1);
        s1 += __shfl_xor_sync(0xffffffffu, s1, 2);
        l0 = l0 * al0 + s0;
        l1 = l1 * al1 + s1;
        m0 = nm0; m1 = nm1;
#pragma unroll
        for (int na = 0; na < 9; na++) {
            O[na][0] *= al0; O[na][1] *= al0;
            O[na][2] *= al1; O[na][3] *= al1;
        }

#pragma unroll
        for (int ks = 0; ks < 2; ks++) {
            const uint32_t a0 = h2pack(Sc[2 * ks][0],     Sc[2 * ks][1]);
            const uint32_t a1 = h2pack(Sc[2 * ks][2],     Sc[2 * ks][3]);
            const uint32_t a2 = h2pack(Sc[2 * ks + 1][0], Sc[2 * ks + 1][1]);
            const uint32_t a3 = h2pack(Sc[2 * ks + 1][2], Sc[2 * ks + 1][3]);
            const int kk = ks * 8 + tg;
#pragma unroll
            for (int na = 0; na < 9; na++) {
                const uint32_t b0 = bV[(na * 8 + g) * 20 + kk];
                const uint32_t b1 = bV[(na * 8 + g) * 20 + kk + 4];
                mma_f16(O[na], a0, a1, a2, a3, b0, b1);
            }
        }

        __syncthreads();
        if (t + 2 < 32) load_tile(t + 2, t & 1);
    }

    const float i0 = 1.0f / l0, i1 = 1.0f / l1;
    const int r0 = qt * 64 + warp * 16 + g;
    uint32_t* out0 = P_AH + (size_t)(b * S_ + r0) * EW + h * DW;
    uint32_t* out1 = P_AH + (size_t)(b * S_ + r0 + 8) * EW + h * DW;
#pragma unroll
    for (int na = 0; na < 9; na++) {
        const int cw = na * 4 + tg;
        out0[cw] = h2pack(O[na][0] * i0, O[na][1] * i0);
        out1[cw] = h2pack(O[na][2] * i1, O[na][3] * i1);
    }
}

// ---------------------------------------------------------------------------
// Output projection (fp16 mma): 3-stage cp.async (R15, proven).
// grid (9, 64), 256 threads.
// ---------------------------------------------------------------------------
#define TQ 72
__global__ void __launch_bounds__(256) out_gemm(const float* __restrict__ bias,
                                                float* __restrict__ outp)
{
    const int rowBase = blockIdx.y * 128;
    const int colBase = blockIdx.x * 128;
    const uint32_t* At = P_AH;
    const uint32_t* Wt = P_OWH;

    __shared__ __align__(16) uint32_t sA[3][128 * 12];
    __shared__ __align__(16) uint32_t sB[3][8 * 136];

    const int tid  = threadIdx.x;
    const int lane = tid & 31, warp = tid >> 5;
    const int wm = warp >> 2, wn = warp & 3;
    const int g = lane >> 2, tg = lane & 3;

    const int rowA = tid >> 1;
    const int kcA  = (tid & 1) * 4;
    const int krB  = tid >> 5;
    const int ncB  = (tid & 31) * 4;

    const uint32_t sAb = smem_u32(&sA[0][0]);
    const uint32_t sBb = smem_u32(&sB[0][0]);

    float acc[4][4][4];
#pragma unroll
    for (int i = 0; i < 4; i++)
#pragma unroll
        for (int j = 0; j < 4; j++)
#pragma unroll
            for (int l = 0; l < 4; l++) acc[i][j][l] = 0.0f;

    auto load_stage = [&](int t) {
        const uint32_t dA = sAb + (uint32_t)(t % 3) * (128 * 12 * 4);
        const uint32_t dB = sBb + (uint32_t)(t % 3) * (8 * 136 * 4);
        cpa16(dA + (rowA * 12 + kcA) * 4,
              At + (size_t)(rowBase + rowA) * EW + t * 8 + kcA);
        cpa16(dB + (krB * 136 + ncB) * 4,
              Wt + (size_t)(t * 8 + krB) * E_ + colBase + ncB);
        asm volatile("cp.async.commit_group;" ::: "memory");
    };

    load_stage(0);
    load_stage(1);

    for (int t = 0; t < TQ; t++) {
        if (t + 1 < TQ)
            asm volatile("cp.async.wait_group 1;" ::: "memory");
        else
            asm volatile("cp.async.wait_group 0;" ::: "memory");
        __syncthreads();
        if (t + 2 < TQ) load_stage(t + 2);

        const uint32_t* As = sA[t % 3];
        const uint32_t* Bv = sB[t % 3];
        uint32_t af[4][4], bf[4][2];
#pragma unroll
        for (int ma = 0; ma < 4; ma++) {
            const int m0 = wm * 64 + ma * 16 + g;
            af[ma][0] = As[m0 * 12 + tg];
            af[ma][1] = As[(m0 + 8) * 12 + tg];
            af[ma][2] = As[m0 * 12 + tg + 4];
            af[ma][3] = As[(m0 + 8) * 12 + tg + 4];
        }
#pragma unroll
        for (int na = 0; na < 4; na++) {
            const int n0 = wn * 32 + na * 8 + g;
            bf[na][0] = Bv[tg * 136 + n0];
            bf[na][1] = Bv[(tg + 4) * 136 + n0];
        }
#pragma unroll
        for (int ma = 0; ma < 4; ma++)
#pragma unroll
            for (int na = 0; na < 4; na++)
                mma_f16(acc[ma][na], af[ma][0], af[ma][1], af[ma][2],
                        af[ma][3], bf[na][0], bf[na][1]);
    }

#pragma unroll
    for (int ma = 0; ma < 4; ma++) {
#pragma unroll
        for (int na = 0; na < 4; na++) {
            const int c = colBase + wn * 32 + na * 8 + 2 * tg;
            const float bx = bias[c];
            const float by = bias[c + 1];
#pragma unroll
            for (int half = 0; half < 2; half++) {
                const int r = rowBase + wm * 64 + ma * 16 + g + half * 8;
                float2 ov;
                ov.x = acc[ma][na][half * 2 + 0] + bx;
                ov.y = acc[ma][na][half * 2 + 1] + by;
                *(float2*)&outp[(size_t)r * E_ + c] = ov;
            }
        }
    }
}

// ---------------------------------------------------------------------------
extern "C" void kernel_launch(void* const* d_in, const int* in_sizes, int n_in,
                              void* d_out, int out_size)
{
    const float* q    = (const float*)d_in[0];
    const float* k    = (const float*)d_in[1];
    const float* v    = (const float*)d_in[2];
    const float* W    = (const float*)d_in[3];
    const float* bias = (const float*)d_in[4];
    const float* ow   = (const float*)d_in[5];
    const float* ob   = (const float*)d_in[6];
    float* out = (float*)d_out;

    cudaFuncSetAttribute(qkv_gemm,
                         cudaFuncAttributeMaxDynamicSharedMemorySize, 56832);

    packW<<<(EW * (W3E / 4) + 255) / 256, 256>>>(W, OFF_W, W3E, W3E / 4,
                                                 EW * (W3E / 4));
    packW<<<(EW * (E_ / 4) + 255) / 256, 256>>>(ow, OFF_OW, E_, E_ / 4,
                                                EW * (E_ / 4));
    const int NX4 = (int)(XW_ / 4);
    packX<<<2048, 256>>>((const float4*)q, OFF_X + 0ull * XW_, NX4);
    packX<<<2048, 256>>>((const float4*)k, OFF_X + 1ull * XW_, NX4);
    packX<<<2048, 256>>>((const float4*)v, OFF_X + 2ull * XW_, NX4);

    qkv_gemm<<<dim3(E_ / 128, NROW / 128, 3), 256, 56832>>>(bias);

    attn_kernel<<<dim3(S_ / 64, H_, B_), 128>>>();

    out_gemm<<<dim3(E_ / 128, NROW / 128), 256>>>(ob, out);
}